// round 3
// baseline (speedup 1.0000x reference)
#include <cuda_runtime.h>
#include <cuda_bf16.h>
#include <math.h>

#define BB 2
#define TT 1024
#define DIM 1024
#define DEPTH 2
#define DSTATE 128
#define HEADDIM 64
#define NHEADS 32
#define DINNER 2048
#define CONVCH 2304
#define DINPROJ 4384
#define VOCAB 256
#define BT (BB*TT)

// ---------------- scratch (device globals; no allocations allowed) ----------
__device__ float g_h  [BT * DIM];       // residual stream
__device__ float g_zx [BT * DINPROJ];   // in_proj output
__device__ float g_xbc[BT * CONVCH];    // conv+silu output
__device__ float g_dt [BT * NHEADS];
__device__ float g_dA [BT * NHEADS];
__device__ float g_y  [BT * DINNER];    // gated scan output

// ---------------- embedding gather ----------------
__global__ void embed_kernel(const int* __restrict__ x,
                             const float* __restrict__ embed,
                             float* __restrict__ h) {
    int bt  = blockIdx.x;
    int tok = x[bt];
    const float4* src = (const float4*)(embed + (size_t)tok * DIM);
    float4*       dst = (float4*)(h + (size_t)bt * DIM);
    dst[threadIdx.x] = src[threadIdx.x];   // 256 threads * float4 = 1024 floats
}

// ---------------- SGEMM: C[M,N] = A[M,K] * B[N,K]^T (+Res) ----------------
// M multiple of 128, K multiple of 8; N guarded.
__global__ void __launch_bounds__(256)
sgemm_tn(int M, int N, int K,
         const float* __restrict__ A,
         const float* __restrict__ B,
         const float* __restrict__ Res,
         float* __restrict__ C) {
    const int BM = 128, BN = 128, BK = 8;
    __shared__ float As[BK][BM];
    __shared__ float Bs[BK][BN];

    int row0 = blockIdx.y * BM;
    int col0 = blockIdx.x * BN;
    int tid  = threadIdx.x;

    int lr = tid >> 1;            // 0..127
    int lc = (tid & 1) << 2;      // 0 or 4
    int tx = tid & 15;
    int ty = tid >> 4;

    float acc[8][8];
#pragma unroll
    for (int i = 0; i < 8; i++)
#pragma unroll
        for (int j = 0; j < 8; j++) acc[i][j] = 0.f;

    const float* Aptr = A + (size_t)(row0 + lr) * K + lc;
    int brow = col0 + lr;
    const float* Bptr = B + (size_t)brow * K + lc;
    bool bvalid = (brow < N);

    for (int k0 = 0; k0 < K; k0 += BK) {
        float4 av = *(const float4*)(Aptr + k0);
        float4 bv = bvalid ? *(const float4*)(Bptr + k0)
                           : make_float4(0.f, 0.f, 0.f, 0.f);
        As[lc + 0][lr] = av.x; As[lc + 1][lr] = av.y;
        As[lc + 2][lr] = av.z; As[lc + 3][lr] = av.w;
        Bs[lc + 0][lr] = bv.x; Bs[lc + 1][lr] = bv.y;
        Bs[lc + 2][lr] = bv.z; Bs[lc + 3][lr] = bv.w;
        __syncthreads();
#pragma unroll
        for (int kk = 0; kk < BK; kk++) {
            float4 a0 = *(const float4*)&As[kk][ty * 8];
            float4 a1 = *(const float4*)&As[kk][ty * 8 + 4];
            float4 b0 = *(const float4*)&Bs[kk][tx * 8];
            float4 b1 = *(const float4*)&Bs[kk][tx * 8 + 4];
            float a[8] = {a0.x, a0.y, a0.z, a0.w, a1.x, a1.y, a1.z, a1.w};
            float b[8] = {b0.x, b0.y, b0.z, b0.w, b1.x, b1.y, b1.z, b1.w};
#pragma unroll
            for (int i = 0; i < 8; i++)
#pragma unroll
                for (int j = 0; j < 8; j++) acc[i][j] = fmaf(a[i], b[j], acc[i][j]);
        }
        __syncthreads();
    }

#pragma unroll
    for (int i = 0; i < 8; i++) {
        int r = row0 + ty * 8 + i;
#pragma unroll
        for (int j = 0; j < 8; j++) {
            int c = col0 + tx * 8 + j;
            if (c < N) {
                float v = acc[i][j];
                if (Res) v += Res[(size_t)r * N + c];
                C[(size_t)r * N + c] = v;
            }
        }
    }
}

// ---------------- causal depthwise conv (K=4) + SiLU ----------------
__global__ void conv_silu_kernel(const float* __restrict__ zx,
                                 const float* __restrict__ cw,
                                 const float* __restrict__ cb,
                                 float* __restrict__ xbc) {
    int idx = blockIdx.x * blockDim.x + threadIdx.x;
    if (idx >= BT * CONVCH) return;
    int c  = idx % CONVCH;
    int bt = idx / CONVCH;
    int t  = bt % TT;
    int b  = bt / TT;
    float acc = cb[c];
#pragma unroll
    for (int k = 0; k < 4; k++) {
        int tt = t - 3 + k;
        if (tt >= 0)
            acc = fmaf(zx[(size_t)(b * TT + tt) * DINPROJ + DINNER + c],
                       cw[c * 4 + k], acc);
    }
    acc = acc / (1.f + expf(-acc));   // silu
    xbc[(size_t)bt * CONVCH + c] = acc;
}

// ---------------- dt = softplus(dt_raw + bias), dA = exp(-exp(Alog)*dt) -----
__global__ void dt_kernel(const float* __restrict__ zx,
                          const float* __restrict__ dtb,
                          const float* __restrict__ alog,
                          float* __restrict__ dt,
                          float* __restrict__ dA) {
    int idx = blockIdx.x * blockDim.x + threadIdx.x;
    if (idx >= BT * NHEADS) return;
    int h  = idx % NHEADS;
    int bt = idx / NHEADS;
    float v = zx[(size_t)bt * DINPROJ + (DINNER + CONVCH) + h] + dtb[h];
    float d = (v > 20.f) ? v : log1pf(expf(v));
    dt[idx] = d;
    dA[idx] = expf(-expf(alog[h]) * d);
}

// ---------------- sequential SSM scan: one warp per (b, head, p) ------------
// lane owns 4 of the DSTATE=128 state entries; reduce over n via shuffles.
// Fuses +D*x and silu(z) gating; writes gated y.
__global__ void __launch_bounds__(256)
scan_kernel(const float* __restrict__ xbc,
            const float* __restrict__ zx,
            const float* __restrict__ dt,
            const float* __restrict__ dA,
            const float* __restrict__ Dw,
            float* __restrict__ y) {
    int gtid = blockIdx.x * blockDim.x + threadIdx.x;
    int w    = gtid >> 5;          // warp id: [0, B*NHEADS*HEADDIM)
    int lane = gtid & 31;
    int b  = w >> 11;              // / (32*64)
    int hp = w & 2047;
    int h  = hp >> 6;
    int p  = hp & 63;

    float4 s = make_float4(0.f, 0.f, 0.f, 0.f);
    float  Dh = Dw[h];
    const float* xb = xbc + (size_t)b * TT * CONVCH;
    const float* zb = zx  + (size_t)b * TT * DINPROJ;
    const int n0 = lane * 4;

    for (int t = 0; t < TT; t++) {
        const float* row = xb + (size_t)t * CONVCH;
        int bth = (b * TT + t) * NHEADS + h;
        float da  = dA[bth];
        float dtv = dt[bth];
        float xv  = row[h * 64 + p];
        float4 Bv = *(const float4*)(row + DINNER + n0);
        float4 Cv = *(const float4*)(row + DINNER + DSTATE + n0);
        float coef = dtv * xv;
        s.x = fmaf(da, s.x, coef * Bv.x);
        s.y = fmaf(da, s.y, coef * Bv.y);
        s.z = fmaf(da, s.z, coef * Bv.z);
        s.w = fmaf(da, s.w, coef * Bv.w);
        float part = s.x * Cv.x + s.y * Cv.y + s.z * Cv.z + s.w * Cv.w;
#pragma unroll
        for (int o = 16; o; o >>= 1)
            part += __shfl_xor_sync(0xFFFFFFFFu, part, o);
        if (lane == 0) {
            float yo = part + Dh * xv;
            float z  = zb[(size_t)t * DINPROJ + h * 64 + p];
            yo *= z / (1.f + expf(-z));
            y[(size_t)(b * TT + t) * DINNER + h * 64 + p] = yo;
        }
    }
}

// ---------------- RMSNorm (in-place), one block per row ----------------
__global__ void rmsnorm_kernel(float* __restrict__ data,
                               const float* __restrict__ w, int n) {
    float* r = data + (size_t)blockIdx.x * n;
    float ss = 0.f;
    for (int i = threadIdx.x; i < n; i += blockDim.x) {
        float v = r[i];
        ss = fmaf(v, v, ss);
    }
#pragma unroll
    for (int o = 16; o; o >>= 1) ss += __shfl_xor_sync(0xFFFFFFFFu, ss, o);
    __shared__ float sh[9];
    int wid = threadIdx.x >> 5, lane = threadIdx.x & 31;
    if (lane == 0) sh[wid] = ss;
    __syncthreads();
    if (wid == 0) {
        float v = (lane < 8) ? sh[lane] : 0.f;
#pragma unroll
        for (int o = 16; o; o >>= 1) v += __shfl_xor_sync(0xFFFFFFFFu, v, o);
        if (lane == 0) sh[8] = rsqrtf(v / n + 1e-5f);
    }
    __syncthreads();
    float sc = sh[8];
    for (int i = threadIdx.x; i < n; i += blockDim.x)
        r[i] = r[i] * sc * w[i];
}

// ---------------- launcher ----------------
extern "C" void kernel_launch(void* const* d_in, const int* in_sizes, int n_in,
                              void* d_out, int out_size) {
    const int*   x            = (const int*)  d_in[0];
    const float* embed        = (const float*)d_in[1];
    const float* in_proj_w    = (const float*)d_in[2];  // [2,4384,1024]
    const float* conv_w       = (const float*)d_in[3];  // [2,2304,4]
    const float* conv_b       = (const float*)d_in[4];  // [2,2304]
    const float* dt_bias      = (const float*)d_in[5];  // [2,32]
    const float* A_log        = (const float*)d_in[6];  // [2,32]
    const float* Dw           = (const float*)d_in[7];  // [2,32]
    const float* gnorm_w      = (const float*)d_in[8];  // [2,2048]
    const float* out_proj_w   = (const float*)d_in[9];  // [2,1024,2048]
    const float* final_norm_w = (const float*)d_in[10]; // [1024]
    float* out = (float*)d_out;

    float *ph, *pzx, *pxbc, *pdt, *pdA, *py;
    cudaGetSymbolAddress((void**)&ph,   g_h);
    cudaGetSymbolAddress((void**)&pzx,  g_zx);
    cudaGetSymbolAddress((void**)&pxbc, g_xbc);
    cudaGetSymbolAddress((void**)&pdt,  g_dt);
    cudaGetSymbolAddress((void**)&pdA,  g_dA);
    cudaGetSymbolAddress((void**)&py,   g_y);

    embed_kernel<<<BT, 256>>>(x, embed, ph);

    for (int l = 0; l < DEPTH; l++) {
        // in_proj: zx = h @ Wp^T      (2048 x 4384 x 1024)
        sgemm_tn<<<dim3((DINPROJ + 127) / 128, BT / 128), 256>>>(
            BT, DINPROJ, DIM, ph, in_proj_w + (size_t)l * DINPROJ * DIM,
            nullptr, pzx);
        // causal conv + silu
        conv_silu_kernel<<<(BT * CONVCH + 255) / 256, 256>>>(
            pzx, conv_w + (size_t)l * CONVCH * 4, conv_b + (size_t)l * CONVCH,
            pxbc);
        // dt / dA
        dt_kernel<<<(BT * NHEADS + 255) / 256, 256>>>(
            pzx, dt_bias + l * NHEADS, A_log + l * NHEADS, pdt, pdA);
        // SSM scan + D*x + silu(z) gating
        scan_kernel<<<(BB * NHEADS * HEADDIM * 32) / 256, 256>>>(
            pxbc, pzx, pdt, pdA, Dw + l * NHEADS, py);
        // group RMSNorm
        rmsnorm_kernel<<<BT, 256>>>(py, gnorm_w + (size_t)l * DINNER, DINNER);
        // out_proj + residual: h = h + y @ Wo^T   (2048 x 1024 x 2048)
        sgemm_tn<<<dim3(DIM / 128, BT / 128), 256>>>(
            BT, DIM, DINNER, py, out_proj_w + (size_t)l * DIM * DINNER,
            ph, ph);
    }

    // final norm + logits = h @ embed^T  (2048 x 256 x 1024)
    rmsnorm_kernel<<<BT, 256>>>(ph, final_norm_w, DIM);
    sgemm_tn<<<dim3(VOCAB / 128, BT / 128), 256>>>(
        BT, VOCAB, DIM, ph, embed, nullptr, out);
}

// round 4
// speedup vs baseline: 2.0973x; 2.0973x over previous
#include <cuda_runtime.h>
#include <cuda_bf16.h>
#include <math.h>
#include <stdint.h>

#define BB 2
#define TT 1024
#define DIM 1024
#define DEPTH 2
#define DSTATE 128
#define HEADDIM 64
#define NHEADS 32
#define DINNER 2048
#define CONVCH 2304
#define DINPROJ 4384
#define VOCAB 256
#define BT (BB*TT)

// ---------------- scratch (device globals; no allocations allowed) ----------
__device__ float g_h  [BT * DIM];
__device__ float g_zx [BT * DINPROJ];
__device__ float g_xbc[BT * CONVCH];
__device__ float g_dt [BT * NHEADS];
__device__ float g_dA [BT * NHEADS];
__device__ float g_y  [BT * DINNER];

// ---------------- embedding gather ----------------
__global__ void embed_kernel(const int* __restrict__ x,
                             const float* __restrict__ embed,
                             float* __restrict__ h) {
    int bt  = blockIdx.x;
    int tok = x[bt];
    const float4* src = (const float4*)(embed + (size_t)tok * DIM);
    float4*       dst = (float4*)(h + (size_t)bt * DIM);
    dst[threadIdx.x] = src[threadIdx.x];
}

// ---------------- tf32 helpers ----------------
__device__ __forceinline__ uint32_t f2tf(float f) {
    uint32_t u;
    asm("cvt.rna.tf32.f32 %0, %1;" : "=r"(u) : "f"(f));
    return u;
}

__device__ __forceinline__ void mma_tf32(float* c,
                                         uint32_t a0, uint32_t a1,
                                         uint32_t a2, uint32_t a3,
                                         uint32_t b0, uint32_t b1) {
    asm volatile(
        "mma.sync.aligned.m16n8k8.row.col.f32.tf32.tf32.f32 "
        "{%0,%1,%2,%3}, {%4,%5,%6,%7}, {%8,%9}, {%0,%1,%2,%3};"
        : "+f"(c[0]), "+f"(c[1]), "+f"(c[2]), "+f"(c[3])
        : "r"(a0), "r"(a1), "r"(a2), "r"(a3), "r"(b0), "r"(b1));
}

// ---------------- TF32 tensor-core GEMM: C[M,N] = A[M,K] B[N,K]^T (+Res) ----
// BM=128, BN=128, BK=16. M % 128 == 0, K % 16 == 0, N even (tail guarded).
// smem holds tiles in mma *fragment order*:
//   A word [mt][ks][lane] = {A(m,k), A(m+8,k), A(m,k+4), A(m+8,k+4)}
//     with m = mt*16 + (lane>>2), k = ks*8 + (lane&3)   -> one LDS.128 / frag
//   B word [nt][ks][lane] = {B(n,k), B(n,k+4)}
//     with n = nt*8 + (lane>>2), k = ks*8 + (lane&3)    -> one LDS.64  / frag
__global__ void __launch_bounds__(256, 2)
gemm_tf32(int M, int N, int K,
          const float* __restrict__ A,
          const float* __restrict__ B,
          const float* __restrict__ Res,
          float* __restrict__ C) {
    __shared__ uint4 AsW[2][512];    // 8 m_tiles * 2 ks * 32 lanes
    __shared__ uint2 BsW[2][1024];   // 16 n_tiles * 2 ks * 32 lanes

    const int tid    = threadIdx.x;
    const int lane   = tid & 31;
    const int wid    = tid >> 5;
    const int warp_m = wid >> 2;     // 0..1  (64 rows each)
    const int warp_n = wid & 3;      // 0..3  (32 cols each)
    const int g      = lane >> 2;    // groupID
    const int q      = lane & 3;     // threadID in group
    const int row0   = blockIdx.y * 128;
    const int col0   = blockIdx.x * 128;
    const int nk     = K >> 4;

    float acc[4][4][4];
#pragma unroll
    for (int i = 0; i < 4; i++)
#pragma unroll
        for (int j = 0; j < 4; j++)
#pragma unroll
            for (int r = 0; r < 4; r++) acc[i][j][r] = 0.f;

    // per-thread global source pointers for the smem words it owns
    const float* pA[2];
    const float* pB[4];
    bool bval[4];
#pragma unroll
    for (int i = 0; i < 2; i++) {
        int w  = tid + 256 * i;
        int lw = w & 31, ks = (w >> 5) & 1, mt = w >> 6;
        int m  = row0 + mt * 16 + (lw >> 2);
        int k  = ks * 8 + (lw & 3);
        pA[i]  = A + (size_t)m * K + k;
    }
#pragma unroll
    for (int i = 0; i < 4; i++) {
        int w  = tid + 256 * i;
        int lw = w & 31, ks = (w >> 5) & 1, nt = w >> 6;
        int n  = col0 + nt * 8 + (lw >> 2);
        int k  = ks * 8 + (lw & 3);
        bval[i] = (n < N);
        pB[i]   = B + (size_t)(bval[i] ? n : 0) * K + k;
    }

    uint32_t sa[2][4];
    uint32_t sb[4][2];

    // ---- prologue: load tile 0 ----
#pragma unroll
    for (int i = 0; i < 2; i++) {
        sa[i][0] = f2tf(pA[i][0]);
        sa[i][1] = f2tf(pA[i][(size_t)8 * K]);
        sa[i][2] = f2tf(pA[i][4]);
        sa[i][3] = f2tf(pA[i][(size_t)8 * K + 4]);
    }
#pragma unroll
    for (int i = 0; i < 4; i++) {
        sb[i][0] = bval[i] ? f2tf(pB[i][0]) : 0u;
        sb[i][1] = bval[i] ? f2tf(pB[i][4]) : 0u;
    }
#pragma unroll
    for (int i = 0; i < 2; i++)
        AsW[0][tid + 256 * i] = make_uint4(sa[i][0], sa[i][1], sa[i][2], sa[i][3]);
#pragma unroll
    for (int i = 0; i < 4; i++)
        BsW[0][tid + 256 * i] = make_uint2(sb[i][0], sb[i][1]);
    __syncthreads();

    for (int kt = 0; kt < nk; kt++) {
        const int cur = kt & 1;
        // ---- prefetch next tile into registers ----
        if (kt + 1 < nk) {
            size_t off = (size_t)(kt + 1) * 16;
#pragma unroll
            for (int i = 0; i < 2; i++) {
                sa[i][0] = f2tf(pA[i][off]);
                sa[i][1] = f2tf(pA[i][off + (size_t)8 * K]);
                sa[i][2] = f2tf(pA[i][off + 4]);
                sa[i][3] = f2tf(pA[i][off + (size_t)8 * K + 4]);
            }
#pragma unroll
            for (int i = 0; i < 4; i++) {
                sb[i][0] = bval[i] ? f2tf(pB[i][off]) : 0u;
                sb[i][1] = bval[i] ? f2tf(pB[i][off + 4]) : 0u;
            }
        }
        // ---- compute on current buffer ----
#pragma unroll
        for (int ks = 0; ks < 2; ks++) {
            uint4 af[4];
            uint2 bf[4];
#pragma unroll
            for (int mt = 0; mt < 4; mt++)
                af[mt] = AsW[cur][(((warp_m * 4 + mt) * 2 + ks) << 5) + lane];
#pragma unroll
            for (int nt = 0; nt < 4; nt++)
                bf[nt] = BsW[cur][(((warp_n * 4 + nt) * 2 + ks) << 5) + lane];
#pragma unroll
            for (int mt = 0; mt < 4; mt++)
#pragma unroll
                for (int nt = 0; nt < 4; nt++)
                    mma_tf32(acc[mt][nt], af[mt].x, af[mt].y, af[mt].z, af[mt].w,
                             bf[nt].x, bf[nt].y);
        }
        // ---- publish next tile ----
        if (kt + 1 < nk) {
            const int nxt = cur ^ 1;
#pragma unroll
            for (int i = 0; i < 2; i++)
                AsW[nxt][tid + 256 * i] =
                    make_uint4(sa[i][0], sa[i][1], sa[i][2], sa[i][3]);
#pragma unroll
            for (int i = 0; i < 4; i++)
                BsW[nxt][tid + 256 * i] = make_uint2(sb[i][0], sb[i][1]);
            __syncthreads();
        }
    }

    // ---- epilogue ----
#pragma unroll
    for (int mt = 0; mt < 4; mt++) {
        int r_lo = row0 + warp_m * 64 + mt * 16 + g;
#pragma unroll
        for (int nt = 0; nt < 4; nt++) {
            int c = col0 + warp_n * 32 + nt * 8 + q * 2;
            if (c < N) {
                float2 v0 = make_float2(acc[mt][nt][0], acc[mt][nt][1]);
                float2 v1 = make_float2(acc[mt][nt][2], acc[mt][nt][3]);
                size_t o0 = (size_t)r_lo * N + c;
                size_t o1 = (size_t)(r_lo + 8) * N + c;
                if (Res) {
                    float2 r0v = *(const float2*)(Res + o0);
                    float2 r1v = *(const float2*)(Res + o1);
                    v0.x += r0v.x; v0.y += r0v.y;
                    v1.x += r1v.x; v1.y += r1v.y;
                }
                *(float2*)(C + o0) = v0;
                *(float2*)(C + o1) = v1;
            }
        }
    }
}

// ---------------- causal depthwise conv (K=4) + SiLU ----------------
__global__ void conv_silu_kernel(const float* __restrict__ zx,
                                 const float* __restrict__ cw,
                                 const float* __restrict__ cb,
                                 float* __restrict__ xbc) {
    int idx = blockIdx.x * blockDim.x + threadIdx.x;
    if (idx >= BT * CONVCH) return;
    int c  = idx % CONVCH;
    int bt = idx / CONVCH;
    int t  = bt % TT;
    int b  = bt / TT;
    float acc = cb[c];
#pragma unroll
    for (int k = 0; k < 4; k++) {
        int tt = t - 3 + k;
        if (tt >= 0)
            acc = fmaf(zx[(size_t)(b * TT + tt) * DINPROJ + DINNER + c],
                       cw[c * 4 + k], acc);
    }
    acc = acc / (1.f + expf(-acc));
    xbc[(size_t)bt * CONVCH + c] = acc;
}

// ---------------- dt = softplus(dt_raw + bias), dA = exp(-exp(Alog)*dt) -----
__global__ void dt_kernel(const float* __restrict__ zx,
                          const float* __restrict__ dtb,
                          const float* __restrict__ alog,
                          float* __restrict__ dt,
                          float* __restrict__ dA) {
    int idx = blockIdx.x * blockDim.x + threadIdx.x;
    if (idx >= BT * NHEADS) return;
    int h  = idx % NHEADS;
    int bt = idx / NHEADS;
    float v = zx[(size_t)bt * DINPROJ + (DINNER + CONVCH) + h] + dtb[h];
    float d = (v > 20.f) ? v : log1pf(expf(v));
    dt[idx] = d;
    dA[idx] = expf(-expf(alog[h]) * d);
}

// ---------------- sequential SSM scan: one warp per (b, head, p) ------------
__global__ void __launch_bounds__(256)
scan_kernel(const float* __restrict__ xbc,
            const float* __restrict__ zx,
            const float* __restrict__ dt,
            const float* __restrict__ dA,
            const float* __restrict__ Dw,
            float* __restrict__ y) {
    int gtid = blockIdx.x * blockDim.x + threadIdx.x;
    int w    = gtid >> 5;
    int lane = gtid & 31;
    int b  = w >> 11;
    int hp = w & 2047;
    int h  = hp >> 6;
    int p  = hp & 63;

    float4 s = make_float4(0.f, 0.f, 0.f, 0.f);
    float  Dh = Dw[h];
    const float* xb = xbc + (size_t)b * TT * CONVCH;
    const float* zb = zx  + (size_t)b * TT * DINPROJ;
    const int n0 = lane * 4;

    for (int t = 0; t < TT; t++) {
        const float* row = xb + (size_t)t * CONVCH;
        int bth = (b * TT + t) * NHEADS + h;
        float da  = dA[bth];
        float dtv = dt[bth];
        float xv  = row[h * 64 + p];
        float4 Bv = *(const float4*)(row + DINNER + n0);
        float4 Cv = *(const float4*)(row + DINNER + DSTATE + n0);
        float coef = dtv * xv;
        s.x = fmaf(da, s.x, coef * Bv.x);
        s.y = fmaf(da, s.y, coef * Bv.y);
        s.z = fmaf(da, s.z, coef * Bv.z);
        s.w = fmaf(da, s.w, coef * Bv.w);
        float part = s.x * Cv.x + s.y * Cv.y + s.z * Cv.z + s.w * Cv.w;
#pragma unroll
        for (int o = 16; o; o >>= 1)
            part += __shfl_xor_sync(0xFFFFFFFFu, part, o);
        if (lane == 0) {
            float yo = part + Dh * xv;
            float z  = zb[(size_t)t * DINPROJ + h * 64 + p];
            yo *= z / (1.f + expf(-z));
            y[(size_t)(b * TT + t) * DINNER + h * 64 + p] = yo;
        }
    }
}

// ---------------- RMSNorm (in-place), one block per row ----------------
__global__ void rmsnorm_kernel(float* __restrict__ data,
                               const float* __restrict__ w, int n) {
    float* r = data + (size_t)blockIdx.x * n;
    float ss = 0.f;
    for (int i = threadIdx.x; i < n; i += blockDim.x) {
        float v = r[i];
        ss = fmaf(v, v, ss);
    }
#pragma unroll
    for (int o = 16; o; o >>= 1) ss += __shfl_xor_sync(0xFFFFFFFFu, ss, o);
    __shared__ float sh[9];
    int wid = threadIdx.x >> 5, lane = threadIdx.x & 31;
    if (lane == 0) sh[wid] = ss;
    __syncthreads();
    if (wid == 0) {
        float v = (lane < 8) ? sh[lane] : 0.f;
#pragma unroll
        for (int o = 16; o; o >>= 1) v += __shfl_xor_sync(0xFFFFFFFFu, v, o);
        if (lane == 0) sh[8] = rsqrtf(v / n + 1e-5f);
    }
    __syncthreads();
    float sc = sh[8];
    for (int i = threadIdx.x; i < n; i += blockDim.x)
        r[i] = r[i] * sc * w[i];
}

// ---------------- launcher ----------------
extern "C" void kernel_launch(void* const* d_in, const int* in_sizes, int n_in,
                              void* d_out, int out_size) {
    const int*   x            = (const int*)  d_in[0];
    const float* embed        = (const float*)d_in[1];
    const float* in_proj_w    = (const float*)d_in[2];
    const float* conv_w       = (const float*)d_in[3];
    const float* conv_b       = (const float*)d_in[4];
    const float* dt_bias      = (const float*)d_in[5];
    const float* A_log        = (const float*)d_in[6];
    const float* Dw           = (const float*)d_in[7];
    const float* gnorm_w      = (const float*)d_in[8];
    const float* out_proj_w   = (const float*)d_in[9];
    const float* final_norm_w = (const float*)d_in[10];
    float* out = (float*)d_out;

    float *ph, *pzx, *pxbc, *pdt, *pdA, *py;
    cudaGetSymbolAddress((void**)&ph,   g_h);
    cudaGetSymbolAddress((void**)&pzx,  g_zx);
    cudaGetSymbolAddress((void**)&pxbc, g_xbc);
    cudaGetSymbolAddress((void**)&pdt,  g_dt);
    cudaGetSymbolAddress((void**)&pdA,  g_dA);
    cudaGetSymbolAddress((void**)&py,   g_y);

    embed_kernel<<<BT, 256>>>(x, embed, ph);

    for (int l = 0; l < DEPTH; l++) {
        gemm_tf32<<<dim3((DINPROJ + 127) / 128, BT / 128), 256>>>(
            BT, DINPROJ, DIM, ph, in_proj_w + (size_t)l * DINPROJ * DIM,
            nullptr, pzx);
        conv_silu_kernel<<<(BT * CONVCH + 255) / 256, 256>>>(
            pzx, conv_w + (size_t)l * CONVCH * 4, conv_b + (size_t)l * CONVCH,
            pxbc);
        dt_kernel<<<(BT * NHEADS + 255) / 256, 256>>>(
            pzx, dt_bias + l * NHEADS, A_log + l * NHEADS, pdt, pdA);
        scan_kernel<<<(BB * NHEADS * HEADDIM * 32) / 256, 256>>>(
            pxbc, pzx, pdt, pdA, Dw + l * NHEADS, py);
        rmsnorm_kernel<<<BT, 256>>>(py, gnorm_w + (size_t)l * DINNER, DINNER);
        gemm_tf32<<<dim3(DIM / 128, BT / 128), 256>>>(
            BT, DIM, DINNER, py, out_proj_w + (size_t)l * DIM * DINNER,
            ph, ph);
    }

    rmsnorm_kernel<<<BT, 256>>>(ph, final_norm_w, DIM);
    gemm_tf32<<<dim3(VOCAB / 128, BT / 128), 256>>>(
        BT, VOCAB, DIM, ph, embed, nullptr, out);
}

// round 5
// speedup vs baseline: 2.3668x; 1.1285x over previous
#include <cuda_runtime.h>
#include <cuda_bf16.h>
#include <math.h>
#include <stdint.h>

#define BB 2
#define TT 1024
#define DIM 1024
#define DEPTH 2
#define DSTATE 128
#define HEADDIM 64
#define NHEADS 32
#define DINNER 2048
#define CONVCH 2304
#define DINPROJ 4384
#define NPAD_IN 4480          // 35*128, padded in_proj rows
#define VOCAB 256
#define BT (BB*TT)

// ---------------- scratch (device globals; no allocations allowed) ----------
__device__ float    g_h  [BT * DIM];
__device__ float    g_zx [BT * DINPROJ];
__device__ float    g_xbc[BT * CONVCH];
__device__ float    g_dt [BT * NHEADS];
__device__ float    g_dA [BT * NHEADS];
__device__ float    g_y  [BT * DINNER];
// tf32 copies
__device__ uint32_t g_win_tf [DEPTH * NPAD_IN * DIM];
__device__ uint32_t g_wout_tf[DEPTH * DIM * DINNER];
__device__ uint32_t g_emb_tf [VOCAB * DIM];
__device__ uint32_t g_h_tf   [BT * DIM];
__device__ uint32_t g_y_tf   [BT * DINNER];

// ---------------- tf32 helpers ----------------
__device__ __forceinline__ uint32_t f2tf(float f) {
    uint32_t u;
    asm("cvt.rna.tf32.f32 %0, %1;" : "=r"(u) : "f"(f));
    return u;
}
__device__ __forceinline__ void mma_tf32(float* c,
                                         uint32_t a0, uint32_t a1,
                                         uint32_t a2, uint32_t a3,
                                         uint32_t b0, uint32_t b1) {
    asm volatile(
        "mma.sync.aligned.m16n8k8.row.col.f32.tf32.tf32.f32 "
        "{%0,%1,%2,%3}, {%4,%5,%6,%7}, {%8,%9}, {%0,%1,%2,%3};"
        : "+f"(c[0]), "+f"(c[1]), "+f"(c[2]), "+f"(c[3])
        : "r"(a0), "r"(a1), "r"(a2), "r"(a3), "r"(b0), "r"(b1));
}
__device__ __forceinline__ void cpa16(uint32_t dst, const void* src) {
    asm volatile("cp.async.cg.shared.global [%0], [%1], 16;"
                 :: "r"(dst), "l"(src));
}

// ---------------- fp32 -> tf32 conversion (with tail zero-pad) -------------
__global__ void cvt_pad(const float* __restrict__ src, uint32_t* __restrict__ dst,
                        long n_src, long n_dst) {
    long i = (long)blockIdx.x * blockDim.x + threadIdx.x;
    if (i >= n_dst) return;
    dst[i] = (i < n_src) ? f2tf(src[i]) : 0u;
}

// ---------------- embedding gather (fp32 + tf32 copies) ----------------
__global__ void embed_kernel(const int* __restrict__ x,
                             const float* __restrict__ embed,
                             float* __restrict__ h,
                             uint32_t* __restrict__ htf) {
    int bt  = blockIdx.x;
    int tok = x[bt];
    const float4* src = (const float4*)(embed + (size_t)tok * DIM);
    float4 v = src[threadIdx.x];
    ((float4*)(h + (size_t)bt * DIM))[threadIdx.x] = v;
    uint32_t* d = htf + (size_t)bt * DIM + threadIdx.x * 4;
    d[0] = f2tf(v.x); d[1] = f2tf(v.y); d[2] = f2tf(v.z); d[3] = f2tf(v.w);
}

// ---------------- TF32 pipelined GEMM: C[M,N] = A[M,K] B[N,K]^T (+Res) -----
// A, B already tf32 (u32). B padded so all row loads valid. BM=BN=128, BK=16.
// smem: 3 stages, each stage = A[128][20] + B[128][20] u32 (stride 20 words:
// 16B-aligned rows for cp.async, conflict-free broadcast fragment gathers).
#define PSTG   3
#define STRIDE 20
#define STG_W  (2 * 128 * STRIDE)   // 5120 u32 per stage
__global__ void __launch_bounds__(256, 2)
gemm_tf32(int M, int N, int K,
          const uint32_t* __restrict__ A,
          const uint32_t* __restrict__ B,
          const float* __restrict__ Res,
          float* __restrict__ C,
          uint32_t* __restrict__ Ctf) {
    extern __shared__ uint32_t sm[];

    const int tid    = threadIdx.x;
    const int lane   = tid & 31;
    const int wid    = tid >> 5;
    const int warp_m = wid >> 2;
    const int warp_n = wid & 3;
    const int g      = lane >> 2;
    const int q      = lane & 3;
    const int row0   = blockIdx.y * 128;
    const int col0   = blockIdx.x * 128;
    const int nk     = K >> 4;

    // this thread's two (row, kq) chunks for A and B
    const int r0c = tid >> 2,        kq0 = tid & 3;
    const int r1c = (tid + 256) >> 2, kq1 = (tid + 256) & 3;
    const uint32_t* gA0 = A + (size_t)(row0 + r0c) * K + kq0 * 4;
    const uint32_t* gA1 = A + (size_t)(row0 + r1c) * K + kq1 * 4;
    const uint32_t* gB0 = B + (size_t)(col0 + r0c) * K + kq0 * 4;
    const uint32_t* gB1 = B + (size_t)(col0 + r1c) * K + kq1 * 4;
    const int dA0 = r0c * STRIDE + kq0 * 4;
    const int dA1 = r1c * STRIDE + kq1 * 4;

    uint32_t smbase = (uint32_t)__cvta_generic_to_shared(sm);

    float acc[4][4][4];
#pragma unroll
    for (int i = 0; i < 4; i++)
#pragma unroll
        for (int j = 0; j < 4; j++)
#pragma unroll
            for (int r = 0; r < 4; r++) acc[i][j][r] = 0.f;

    // ---- prologue: issue tiles 0..PSTG-2 ----
#pragma unroll
    for (int p = 0; p < PSTG - 1; p++) {
        uint32_t sb = smbase + p * STG_W * 4;
        size_t ko = (size_t)p * 16;
        cpa16(sb + dA0 * 4,                   gA0 + ko);
        cpa16(sb + dA1 * 4,                   gA1 + ko);
        cpa16(sb + (2560 + dA0) * 4,          gB0 + ko);
        cpa16(sb + (2560 + dA1) * 4,          gB1 + ko);
        asm volatile("cp.async.commit_group;");
    }

    for (int kt = 0; kt < nk; kt++) {
        asm volatile("cp.async.wait_group %0;" :: "n"(PSTG - 2));
        __syncthreads();

        // issue tile kt+PSTG-1
        if (kt + PSTG - 1 < nk) {
            int st = (kt + PSTG - 1) % PSTG;
            uint32_t sb = smbase + st * STG_W * 4;
            size_t ko = (size_t)(kt + PSTG - 1) * 16;
            cpa16(sb + dA0 * 4,          gA0 + ko);
            cpa16(sb + dA1 * 4,          gA1 + ko);
            cpa16(sb + (2560 + dA0) * 4, gB0 + ko);
            cpa16(sb + (2560 + dA1) * 4, gB1 + ko);
        }
        asm volatile("cp.async.commit_group;");

        // compute tile kt
        const uint32_t* Ab = sm + (kt % PSTG) * STG_W;
        const uint32_t* Bb = Ab + 2560;
#pragma unroll
        for (int ks = 0; ks < 2; ks++) {
            const int kb = ks * 8 + q;
            uint32_t af[4][4];
            uint32_t bf[4][2];
#pragma unroll
            for (int mt = 0; mt < 4; mt++) {
                int rm = warp_m * 64 + mt * 16 + g;
                af[mt][0] = Ab[rm * STRIDE + kb];
                af[mt][1] = Ab[(rm + 8) * STRIDE + kb];
                af[mt][2] = Ab[rm * STRIDE + kb + 4];
                af[mt][3] = Ab[(rm + 8) * STRIDE + kb + 4];
            }
#pragma unroll
            for (int nt = 0; nt < 4; nt++) {
                int rn = warp_n * 32 + nt * 8 + g;
                bf[nt][0] = Bb[rn * STRIDE + kb];
                bf[nt][1] = Bb[rn * STRIDE + kb + 4];
            }
#pragma unroll
            for (int mt = 0; mt < 4; mt++)
#pragma unroll
                for (int nt = 0; nt < 4; nt++)
                    mma_tf32(acc[mt][nt], af[mt][0], af[mt][1], af[mt][2],
                             af[mt][3], bf[nt][0], bf[nt][1]);
        }
        __syncthreads();
    }

    // ---- epilogue ----
#pragma unroll
    for (int mt = 0; mt < 4; mt++) {
        int r_lo = row0 + warp_m * 64 + mt * 16 + g;
#pragma unroll
        for (int nt = 0; nt < 4; nt++) {
            int c = col0 + warp_n * 32 + nt * 8 + q * 2;
            if (c < N) {
                float2 v0 = make_float2(acc[mt][nt][0], acc[mt][nt][1]);
                float2 v1 = make_float2(acc[mt][nt][2], acc[mt][nt][3]);
                size_t o0 = (size_t)r_lo * N + c;
                size_t o1 = (size_t)(r_lo + 8) * N + c;
                if (Res) {
                    float2 r0v = *(const float2*)(Res + o0);
                    float2 r1v = *(const float2*)(Res + o1);
                    v0.x += r0v.x; v0.y += r0v.y;
                    v1.x += r1v.x; v1.y += r1v.y;
                }
                *(float2*)(C + o0) = v0;
                *(float2*)(C + o1) = v1;
                if (Ctf) {
                    Ctf[o0] = f2tf(v0.x); Ctf[o0 + 1] = f2tf(v0.y);
                    Ctf[o1] = f2tf(v1.x); Ctf[o1 + 1] = f2tf(v1.y);
                }
            }
        }
    }
}

// ---------------- causal depthwise conv (K=4) + SiLU ----------------
__global__ void conv_silu_kernel(const float* __restrict__ zx,
                                 const float* __restrict__ cw,
                                 const float* __restrict__ cb,
                                 float* __restrict__ xbc) {
    int c  = blockIdx.x * blockDim.x + threadIdx.x;   // < CONVCH
    int bt = blockIdx.y;
    int t  = bt % TT;
    int b  = bt / TT;
    float acc = cb[c];
#pragma unroll
    for (int k = 0; k < 4; k++) {
        int tt = t - 3 + k;
        if (tt >= 0)
            acc = fmaf(zx[(size_t)(b * TT + tt) * DINPROJ + DINNER + c],
                       cw[c * 4 + k], acc);
    }
    acc = acc / (1.f + expf(-acc));
    xbc[(size_t)bt * CONVCH + c] = acc;
}

// ---------------- dt = softplus(dt_raw + bias), dA = exp(-exp(Alog)*dt) -----
__global__ void dt_kernel(const float* __restrict__ zx,
                          const float* __restrict__ dtb,
                          const float* __restrict__ alog,
                          float* __restrict__ dt,
                          float* __restrict__ dA) {
    int idx = blockIdx.x * blockDim.x + threadIdx.x;
    if (idx >= BT * NHEADS) return;
    int h  = idx % NHEADS;
    int bt = idx / NHEADS;
    float v = zx[(size_t)bt * DINPROJ + (DINNER + CONVCH) + h] + dtb[h];
    float d = (v > 20.f) ? v : log1pf(expf(v));
    dt[idx] = d;
    dA[idx] = expf(-expf(alog[h]) * d);
}

// ---------------- sequential SSM scan: one warp per (b, head, p) ------------
__global__ void __launch_bounds__(256)
scan_kernel(const float* __restrict__ xbc,
            const float* __restrict__ zx,
            const float* __restrict__ dt,
            const float* __restrict__ dA,
            const float* __restrict__ Dw,
            float* __restrict__ y) {
    int gtid = blockIdx.x * blockDim.x + threadIdx.x;
    int w    = gtid >> 5;
    int lane = gtid & 31;
    int b  = w >> 11;
    int hp = w & 2047;
    int h  = hp >> 6;
    int p  = hp & 63;

    float4 s = make_float4(0.f, 0.f, 0.f, 0.f);
    float  Dh = Dw[h];
    const float* xb = xbc + (size_t)b * TT * CONVCH;
    const float* zb = zx  + (size_t)b * TT * DINPROJ;
    const int n0 = lane * 4;

    for (int t = 0; t < TT; t++) {
        const float* row = xb + (size_t)t * CONVCH;
        int bth = (b * TT + t) * NHEADS + h;
        float da  = dA[bth];
        float dtv = dt[bth];
        float xv  = row[h * 64 + p];
        float4 Bv = *(const float4*)(row + DINNER + n0);
        float4 Cv = *(const float4*)(row + DINNER + DSTATE + n0);
        float coef = dtv * xv;
        s.x = fmaf(da, s.x, coef * Bv.x);
        s.y = fmaf(da, s.y, coef * Bv.y);
        s.z = fmaf(da, s.z, coef * Bv.z);
        s.w = fmaf(da, s.w, coef * Bv.w);
        float part = s.x * Cv.x + s.y * Cv.y + s.z * Cv.z + s.w * Cv.w;
#pragma unroll
        for (int o = 16; o; o >>= 1)
            part += __shfl_xor_sync(0xFFFFFFFFu, part, o);
        if (lane == 0) {
            float yo = part + Dh * xv;
            float z  = zb[(size_t)t * DINPROJ + h * 64 + p];
            yo *= z / (1.f + expf(-z));
            y[(size_t)(b * TT + t) * DINNER + h * 64 + p] = yo;
        }
    }
}

// ---------------- RMSNorm (in-place) + tf32 copy, one block per row --------
__global__ void rmsnorm_kernel(float* __restrict__ data,
                               const float* __restrict__ w, int n,
                               uint32_t* __restrict__ tf) {
    float* r = data + (size_t)blockIdx.x * n;
    uint32_t* rt = tf + (size_t)blockIdx.x * n;
    float ss = 0.f;
    for (int i = threadIdx.x; i < n; i += blockDim.x) {
        float v = r[i];
        ss = fmaf(v, v, ss);
    }
#pragma unroll
    for (int o = 16; o; o >>= 1) ss += __shfl_xor_sync(0xFFFFFFFFu, ss, o);
    __shared__ float sh[9];
    int wid = threadIdx.x >> 5, lane = threadIdx.x & 31;
    if (lane == 0) sh[wid] = ss;
    __syncthreads();
    if (wid == 0) {
        float v = (lane < 8) ? sh[lane] : 0.f;
#pragma unroll
        for (int o = 16; o; o >>= 1) v += __shfl_xor_sync(0xFFFFFFFFu, v, o);
        if (lane == 0) sh[8] = rsqrtf(v / n + 1e-5f);
    }
    __syncthreads();
    float sc = sh[8];
    for (int i = threadIdx.x; i < n; i += blockDim.x) {
        float v = r[i] * sc * w[i];
        r[i]  = v;
        rt[i] = f2tf(v);
    }
}

// ---------------- launcher ----------------
extern "C" void kernel_launch(void* const* d_in, const int* in_sizes, int n_in,
                              void* d_out, int out_size) {
    const int*   x            = (const int*)  d_in[0];
    const float* embed        = (const float*)d_in[1];
    const float* in_proj_w    = (const float*)d_in[2];
    const float* conv_w       = (const float*)d_in[3];
    const float* conv_b       = (const float*)d_in[4];
    const float* dt_bias      = (const float*)d_in[5];
    const float* A_log        = (const float*)d_in[6];
    const float* Dw           = (const float*)d_in[7];
    const float* gnorm_w      = (const float*)d_in[8];
    const float* out_proj_w   = (const float*)d_in[9];
    const float* final_norm_w = (const float*)d_in[10];
    float* out = (float*)d_out;

    float *ph, *pzx, *pxbc, *pdt, *pdA, *py;
    uint32_t *pwin, *pwout, *pemb, *phtf, *pytf;
    cudaGetSymbolAddress((void**)&ph,    g_h);
    cudaGetSymbolAddress((void**)&pzx,   g_zx);
    cudaGetSymbolAddress((void**)&pxbc,  g_xbc);
    cudaGetSymbolAddress((void**)&pdt,   g_dt);
    cudaGetSymbolAddress((void**)&pdA,   g_dA);
    cudaGetSymbolAddress((void**)&py,    g_y);
    cudaGetSymbolAddress((void**)&pwin,  g_win_tf);
    cudaGetSymbolAddress((void**)&pwout, g_wout_tf);
    cudaGetSymbolAddress((void**)&pemb,  g_emb_tf);
    cudaGetSymbolAddress((void**)&phtf,  g_h_tf);
    cudaGetSymbolAddress((void**)&pytf,  g_y_tf);

    static bool attr_set = false;
    cudaFuncSetAttribute(gemm_tf32, cudaFuncAttributeMaxDynamicSharedMemorySize,
                         PSTG * STG_W * 4);
    (void)attr_set;
    const int SMEMB = PSTG * STG_W * 4;

    // weight / embedding tf32 conversion (deterministic, every launch)
    for (int l = 0; l < DEPTH; l++) {
        long nsrc = (long)DINPROJ * DIM, ndst = (long)NPAD_IN * DIM;
        cvt_pad<<<(int)((ndst + 255) / 256), 256>>>(
            in_proj_w + (size_t)l * DINPROJ * DIM,
            pwin + (size_t)l * NPAD_IN * DIM, nsrc, ndst);
    }
    {
        long n = (long)DEPTH * DIM * DINNER;
        cvt_pad<<<(int)((n + 255) / 256), 256>>>(out_proj_w, pwout, n, n);
        long e = (long)VOCAB * DIM;
        cvt_pad<<<(int)((e + 255) / 256), 256>>>(embed, pemb, e, e);
    }

    embed_kernel<<<BT, 256>>>(x, embed, ph, phtf);

    for (int l = 0; l < DEPTH; l++) {
        gemm_tf32<<<dim3(NPAD_IN / 128, BT / 128), 256, SMEMB>>>(
            BT, DINPROJ, DIM, phtf, pwin + (size_t)l * NPAD_IN * DIM,
            nullptr, pzx, nullptr);
        conv_silu_kernel<<<dim3(CONVCH / 256, BT), 256>>>(
            pzx, conv_w + (size_t)l * CONVCH * 4, conv_b + (size_t)l * CONVCH,
            pxbc);
        dt_kernel<<<(BT * NHEADS + 255) / 256, 256>>>(
            pzx, dt_bias + l * NHEADS, A_log + l * NHEADS, pdt, pdA);
        scan_kernel<<<(BB * NHEADS * HEADDIM * 32) / 256, 256>>>(
            pxbc, pzx, pdt, pdA, Dw + l * NHEADS, py);
        rmsnorm_kernel<<<BT, 256>>>(py, gnorm_w + (size_t)l * DINNER, DINNER,
                                    pytf);
        gemm_tf32<<<dim3(DIM / 128, BT / 128), 256, SMEMB>>>(
            BT, DIM, DINNER, pytf, pwout + (size_t)l * DIM * DINNER,
            ph, ph, phtf);
    }

    rmsnorm_kernel<<<BT, 256>>>(ph, final_norm_w, DIM, phtf);
    gemm_tf32<<<dim3(VOCAB / 128, BT / 128), 256, SMEMB>>>(
        BT, VOCAB, DIM, phtf, pemb, nullptr, out, nullptr);
}

// round 7
// speedup vs baseline: 2.4223x; 1.0234x over previous
#include <cuda_runtime.h>
#include <cuda_bf16.h>
#include <math.h>
#include <stdint.h>

#define BB 2
#define TT 1024
#define DIM 1024
#define DEPTH 2
#define DSTATE 128
#define HEADDIM 64
#define NHEADS 32
#define DINNER 2048
#define CONVCH 2304
#define DINPROJ 4384
#define NPAD_IN 4480          // 35*128 padded in_proj rows
#define VOCAB 256
#define BT (BB*TT)

// ---------------- scratch (device globals; no allocations allowed) ----------
__device__ float g_h  [BT * DIM];
__device__ float g_zx [BT * DINPROJ];
__device__ float g_xbc[BT * CONVCH];
__device__ float g_dt [BT * NHEADS];
__device__ float g_dA [BT * NHEADS];
__device__ float g_y  [BT * DINNER];
// fragment-packed tf32 operands
//  A-pack words: (M/16)*(K/32)*4*32  uint4
//  B-pack words: (N/8)*(K/32)*2*32   uint4
__device__ uint4 g_win_pk [DEPTH * (NPAD_IN/8) * (DIM/32)    * 64];
__device__ uint4 g_wout_pk[DEPTH * (DIM/8)     * (DINNER/32) * 64];
__device__ uint4 g_emb_pk [(VOCAB/8) * (DIM/32) * 64];
__device__ uint4 g_h_pk   [(BT/16) * (DIM/32)    * 128];
__device__ uint4 g_y_pk   [(BT/16) * (DINNER/32) * 128];

// ---------------- helpers ----------------
__device__ __forceinline__ uint32_t f2tf(float f) {
    uint32_t u;
    asm("cvt.rna.tf32.f32 %0, %1;" : "=r"(u) : "f"(f));
    return u;
}
__device__ __forceinline__ void mma_tf32(float* c,
                                         uint32_t a0, uint32_t a1,
                                         uint32_t a2, uint32_t a3,
                                         uint32_t b0, uint32_t b1) {
    asm volatile(
        "mma.sync.aligned.m16n8k8.row.col.f32.tf32.tf32.f32 "
        "{%0,%1,%2,%3}, {%4,%5,%6,%7}, {%8,%9}, {%0,%1,%2,%3};"
        : "+f"(c[0]), "+f"(c[1]), "+f"(c[2]), "+f"(c[3])
        : "r"(a0), "r"(a1), "r"(a2), "r"(a3), "r"(b0), "r"(b1));
}
__device__ __forceinline__ void cpa16(uint32_t dst, const void* src) {
    asm volatile("cp.async.cg.shared.global [%0], [%1], 16;"
                 :: "r"(dst), "l"(src));
}
__device__ __forceinline__ uint32_t smem_u32(const void* p) {
    uint32_t a;
    asm("{ .reg .u64 t; cvta.to.shared.u64 t, %1; cvt.u32.u64 %0, t; }"
        : "=r"(a) : "l"(p));
    return a;
}

// ---------------- activation pack: fp32 row-major -> fragment order --------
// word idx = ((mt*(K/32)+kt)*4 + ks)*32 + lane
// word = {A(16mt+g, k0), A(16mt+g+8, k0), A(16mt+g, k0+4), A(16mt+g+8, k0+4)}
//   g=lane>>2, q=lane&3, k0 = 32kt + 8ks + q
__global__ void pack_a(const float* __restrict__ A, uint4* __restrict__ P,
                       int K) {
    int idx  = blockIdx.x * 256 + threadIdx.x;
    int lane = idx & 31;
    int t2   = idx >> 5;
    int ks   = t2 & 3;
    int t3   = t2 >> 2;
    int ktn  = K >> 5;
    int kt   = t3 % ktn;
    int mt   = t3 / ktn;
    int g = lane >> 2, q = lane & 3;
    const float* r0 = A + (size_t)(mt * 16 + g) * K + kt * 32 + ks * 8 + q;
    const float* r1 = r0 + (size_t)8 * K;
    P[idx] = make_uint4(f2tf(r0[0]), f2tf(r1[0]), f2tf(r0[4]), f2tf(r1[4]));
}

// ---------------- weight pack: fp32 row-major [Nsrc,K] -> fragment order ---
// word idx = ((nt*(K/32)+kt)*2 + kp)*32 + lane
// word = {B(n,k0), B(n,k0+4), B(n,k0+8), B(n,k0+12)}  n=8nt+g, k0=32kt+16kp+q
__global__ void pack_b(const float* __restrict__ B, uint4* __restrict__ P,
                       int K, int Nsrc) {
    int idx  = blockIdx.x * 256 + threadIdx.x;
    int lane = idx & 31;
    int t2   = idx >> 5;
    int kp   = t2 & 1;
    int t3   = t2 >> 1;
    int ktn  = K >> 5;
    int kt   = t3 % ktn;
    int nt   = t3 / ktn;
    int g = lane >> 2, q = lane & 3;
    int n  = nt * 8 + g;
    uint4 w = make_uint4(0u, 0u, 0u, 0u);
    if (n < Nsrc) {
        const float* r = B + (size_t)n * K + kt * 32 + kp * 16 + q;
        w = make_uint4(f2tf(r[0]), f2tf(r[4]), f2tf(r[8]), f2tf(r[12]));
    }
    P[idx] = w;
}

// ---------------- embedding gather ----------------
__global__ void embed_kernel(const int* __restrict__ x,
                             const float* __restrict__ embed,
                             float* __restrict__ h) {
    int bt  = blockIdx.x;
    int tok = x[bt];
    const float4* src = (const float4*)(embed + (size_t)tok * DIM);
    ((float4*)(h + (size_t)bt * DIM))[threadIdx.x] = src[threadIdx.x];
}

// ---------------- packed tf32 GEMM: C[M,N] = A[M,K] B[N,K]^T (+Res) --------
// Apk/Bpk fragment-packed. Tile 128x128, BK=32, 3-stage cp.async pipeline.
// stage = A 1024 uint4 (16KB) + B 1024 uint4 (16KB)
#define ST_W4     2048
#define SMEM_GEMM (3 * ST_W4 * 16)   // 96KB

__global__ void __launch_bounds__(256, 2)
gemm_pk(int N, int K,
        const uint4* __restrict__ Apk,
        const uint4* __restrict__ Bpk,
        const float* __restrict__ Res,
        float* __restrict__ C) {
    extern __shared__ uint4 sm4[];
    const uint32_t sbase = smem_u32(sm4);

    const int tid    = threadIdx.x;
    const int lane   = tid & 31;
    const int wid    = tid >> 5;
    const int warp_m = wid >> 2;       // 0..1
    const int warp_n = wid & 3;        // 0..3
    const int g      = lane >> 2;
    const int q      = lane & 3;
    const int row0   = blockIdx.y * 128;
    const int col0   = blockIdx.x * 128;
    const int ktn    = K >> 5;

    // per-thread cp.async chunks: 4 A + 4 B
    const uint4* asrc[4];
    const uint4* bsrc[4];
    uint32_t adst[4], bdst[4];
#pragma unroll
    for (int i = 0; i < 4; i++) {
        int ca = tid + 256 * i;                 // 0..1023
        int mt = ca >> 7, ia = ca & 127;
        asrc[i] = Apk + ((size_t)(row0 / 16 + mt) * ktn) * 128 + ia;
        adst[i] = ca;
        int nt = ca >> 6, ib = ca & 63;
        bsrc[i] = Bpk + ((size_t)(col0 / 8 + nt) * ktn) * 64 + ib;
        bdst[i] = 1024 + ca;
    }

    float acc[4][4][4];
#pragma unroll
    for (int i = 0; i < 4; i++)
#pragma unroll
        for (int j = 0; j < 4; j++)
#pragma unroll
            for (int r = 0; r < 4; r++) acc[i][j][r] = 0.f;

    // prologue: stages 0,1
#pragma unroll
    for (int p = 0; p < 2; p++) {
        uint32_t sb = sbase + p * ST_W4 * 16;
#pragma unroll
        for (int i = 0; i < 4; i++) cpa16(sb + adst[i] * 16, asrc[i] + p * 128);
#pragma unroll
        for (int i = 0; i < 4; i++) cpa16(sb + bdst[i] * 16, bsrc[i] + p * 64);
        asm volatile("cp.async.commit_group;");
    }

    for (int kt = 0; kt < ktn; kt++) {
        asm volatile("cp.async.wait_group 1;");
        __syncthreads();

        if (kt + 2 < ktn) {
            uint32_t sb = sbase + ((kt + 2) % 3) * ST_W4 * 16;
            size_t ao = (size_t)(kt + 2) * 128;
            size_t bo = (size_t)(kt + 2) * 64;
#pragma unroll
            for (int i = 0; i < 4; i++) cpa16(sb + adst[i] * 16, asrc[i] + ao);
#pragma unroll
            for (int i = 0; i < 4; i++) cpa16(sb + bdst[i] * 16, bsrc[i] + bo);
        }
        asm volatile("cp.async.commit_group;");

        const uint4* Ab = sm4 + (kt % 3) * ST_W4;
        const uint4* Bb = Ab + 1024;
#pragma unroll
        for (int kp = 0; kp < 2; kp++) {
            uint4 bw[4];
#pragma unroll
            for (int nt = 0; nt < 4; nt++)
                bw[nt] = Bb[((warp_n * 4 + nt) * 2 + kp) * 32 + lane];
#pragma unroll
            for (int hl = 0; hl < 2; hl++) {
                const int ks = kp * 2 + hl;
                uint4 af[4];
#pragma unroll
                for (int mt = 0; mt < 4; mt++)
                    af[mt] = Ab[((warp_m * 4 + mt) * 4 + ks) * 32 + lane];
#pragma unroll
                for (int mt = 0; mt < 4; mt++)
#pragma unroll
                    for (int nt = 0; nt < 4; nt++) {
                        uint32_t b0 = hl ? bw[nt].z : bw[nt].x;
                        uint32_t b1 = hl ? bw[nt].w : bw[nt].y;
                        mma_tf32(acc[mt][nt], af[mt].x, af[mt].y, af[mt].z,
                                 af[mt].w, b0, b1);
                    }
            }
        }
    }

    // epilogue (fragment mapping validated in R4)
#pragma unroll
    for (int mt = 0; mt < 4; mt++) {
        int r_lo = row0 + warp_m * 64 + mt * 16 + g;
#pragma unroll
        for (int nt = 0; nt < 4; nt++) {
            int c = col0 + warp_n * 32 + nt * 8 + q * 2;
            if (c < N) {
                float2 v0 = make_float2(acc[mt][nt][0], acc[mt][nt][1]);
                float2 v1 = make_float2(acc[mt][nt][2], acc[mt][nt][3]);
                size_t o0 = (size_t)r_lo * N + c;
                size_t o1 = (size_t)(r_lo + 8) * N + c;
                if (Res) {
                    float2 r0v = *(const float2*)(Res + o0);
                    float2 r1v = *(const float2*)(Res + o1);
                    v0.x += r0v.x; v0.y += r0v.y;
                    v1.x += r1v.x; v1.y += r1v.y;
                }
                *(float2*)(C + o0) = v0;
                *(float2*)(C + o1) = v1;
            }
        }
    }
}

// ---------------- causal depthwise conv (K=4) + SiLU ----------------
__global__ void conv_silu_kernel(const float* __restrict__ zx,
                                 const float* __restrict__ cw,
                                 const float* __restrict__ cb,
                                 float* __restrict__ xbc) {
    int c  = blockIdx.x * blockDim.x + threadIdx.x;
    int bt = blockIdx.y;
    int t  = bt % TT;
    int b  = bt / TT;
    float acc = cb[c];
#pragma unroll
    for (int k = 0; k < 4; k++) {
        int tt = t - 3 + k;
        if (tt >= 0)
            acc = fmaf(zx[(size_t)(b * TT + tt) * DINPROJ + DINNER + c],
                       cw[c * 4 + k], acc);
    }
    acc = acc / (1.f + expf(-acc));
    xbc[(size_t)bt * CONVCH + c] = acc;
}

// ---------------- dt = softplus(dt_raw + bias), dA = exp(-exp(Alog)*dt) -----
__global__ void dt_kernel(const float* __restrict__ zx,
                          const float* __restrict__ dtb,
                          const float* __restrict__ alog,
                          float* __restrict__ dt,
                          float* __restrict__ dA) {
    int idx = blockIdx.x * blockDim.x + threadIdx.x;
    if (idx >= BT * NHEADS) return;
    int h  = idx % NHEADS;
    int bt = idx / NHEADS;
    float v = zx[(size_t)bt * DINPROJ + (DINNER + CONVCH) + h] + dtb[h];
    float d = (v > 20.f) ? v : log1pf(expf(v));
    dt[idx] = d;
    dA[idx] = expf(-expf(alog[h]) * d);
}

// ---------------- sequential SSM scan: one warp per (b, head, p) ------------
__global__ void __launch_bounds__(256)
scan_kernel(const float* __restrict__ xbc,
            const float* __restrict__ zx,
            const float* __restrict__ dt,
            const float* __restrict__ dA,
            const float* __restrict__ Dw,
            float* __restrict__ y) {
    int gtid = blockIdx.x * blockDim.x + threadIdx.x;
    int w    = gtid >> 5;
    int lane = gtid & 31;
    int b  = w >> 11;
    int hp = w & 2047;
    int h  = hp >> 6;
    int p  = hp & 63;

    float4 s = make_float4(0.f, 0.f, 0.f, 0.f);
    float  Dh = Dw[h];
    const float* xb = xbc + (size_t)b * TT * CONVCH;
    const float* zb = zx  + (size_t)b * TT * DINPROJ;
    const int n0 = lane * 4;

    for (int t = 0; t < TT; t++) {
        const float* row = xb + (size_t)t * CONVCH;
        int bth = (b * TT + t) * NHEADS + h;
        float da  = dA[bth];
        float dtv = dt[bth];
        float xv  = row[h * 64 + p];
        float4 Bv = *(const float4*)(row + DINNER + n0);
        float4 Cv = *(const float4*)(row + DINNER + DSTATE + n0);
        float coef = dtv * xv;
        s.x = fmaf(da, s.x, coef * Bv.x);
        s.y = fmaf(da, s.y, coef * Bv.y);
        s.z = fmaf(da, s.z, coef * Bv.z);
        s.w = fmaf(da, s.w, coef * Bv.w);
        float part = s.x * Cv.x + s.y * Cv.y + s.z * Cv.z + s.w * Cv.w;
#pragma unroll
        for (int o = 16; o; o >>= 1)
            part += __shfl_xor_sync(0xFFFFFFFFu, part, o);
        if (lane == 0) {
            float yo = part + Dh * xv;
            float z  = zb[(size_t)t * DINPROJ + h * 64 + p];
            yo *= z / (1.f + expf(-z));
            y[(size_t)(b * TT + t) * DINNER + h * 64 + p] = yo;
        }
    }
}

// ---------------- RMSNorm (in-place), one block per row ----------------
__global__ void rmsnorm_kernel(float* __restrict__ data,
                               const float* __restrict__ w, int n) {
    float* r = data + (size_t)blockIdx.x * n;
    float ss = 0.f;
    for (int i = threadIdx.x; i < n; i += blockDim.x) {
        float v = r[i];
        ss = fmaf(v, v, ss);
    }
#pragma unroll
    for (int o = 16; o; o >>= 1) ss += __shfl_xor_sync(0xFFFFFFFFu, ss, o);
    __shared__ float sh[9];
    int wid = threadIdx.x >> 5, lane = threadIdx.x & 31;
    if (lane == 0) sh[wid] = ss;
    __syncthreads();
    if (wid == 0) {
        float v = (lane < 8) ? sh[lane] : 0.f;
#pragma unroll
        for (int o = 16; o; o >>= 1) v += __shfl_xor_sync(0xFFFFFFFFu, v, o);
        if (lane == 0) sh[8] = rsqrtf(v / n + 1e-5f);
    }
    __syncthreads();
    float sc = sh[8];
    for (int i = threadIdx.x; i < n; i += blockDim.x)
        r[i] = r[i] * sc * w[i];
}

// ---------------- launcher ----------------
extern "C" void kernel_launch(void* const* d_in, const int* in_sizes, int n_in,
                              void* d_out, int out_size) {
    const int*   x            = (const int*)  d_in[0];
    const float* embed        = (const float*)d_in[1];
    const float* in_proj_w    = (const float*)d_in[2];
    const float* conv_w       = (const float*)d_in[3];
    const float* conv_b       = (const float*)d_in[4];
    const float* dt_bias      = (const float*)d_in[5];
    const float* A_log        = (const float*)d_in[6];
    const float* Dw           = (const float*)d_in[7];
    const float* gnorm_w      = (const float*)d_in[8];
    const float* out_proj_w   = (const float*)d_in[9];
    const float* final_norm_w = (const float*)d_in[10];
    float* out = (float*)d_out;

    float *ph, *pzx, *pxbc, *pdt, *pdA, *py;
    uint4 *pwin, *pwout, *pemb, *phpk, *pypk;
    cudaGetSymbolAddress((void**)&ph,    g_h);
    cudaGetSymbolAddress((void**)&pzx,   g_zx);
    cudaGetSymbolAddress((void**)&pxbc,  g_xbc);
    cudaGetSymbolAddress((void**)&pdt,   g_dt);
    cudaGetSymbolAddress((void**)&pdA,   g_dA);
    cudaGetSymbolAddress((void**)&py,    g_y);
    cudaGetSymbolAddress((void**)&pwin,  g_win_pk);
    cudaGetSymbolAddress((void**)&pwout, g_wout_pk);
    cudaGetSymbolAddress((void**)&pemb,  g_emb_pk);
    cudaGetSymbolAddress((void**)&phpk,  g_h_pk);
    cudaGetSymbolAddress((void**)&pypk,  g_y_pk);

    cudaFuncSetAttribute(gemm_pk, cudaFuncAttributeMaxDynamicSharedMemorySize,
                         SMEM_GEMM);

    const int WIN_W  = (NPAD_IN / 8) * (DIM / 32) * 64;     // per layer
    const int WOUT_W = (DIM / 8) * (DINNER / 32) * 64;      // per layer
    const int HPK_B  = (BT / 16) * (DIM / 32) * 128 / 256;  // 2048 blocks
    const int YPK_B  = (BT / 16) * (DINNER / 32) * 128 / 256;

    // launches 1-5 (so launch 6 = first big GEMM, for ncu -s 5 -c 1)
    pack_b<<<WIN_W / 256, 256>>>(in_proj_w, pwin, DIM, DINPROJ);
    pack_b<<<(VOCAB / 8) * (DIM / 32) * 64 / 256, 256>>>(embed, pemb, DIM,
                                                         VOCAB);
    embed_kernel<<<BT, 256>>>(x, embed, ph);
    pack_a<<<HPK_B, 256>>>(ph, phpk, DIM);
    pack_b<<<WIN_W / 256, 256>>>(in_proj_w + (size_t)DINPROJ * DIM,
                                 pwin + WIN_W, DIM, DINPROJ);

    for (int l = 0; l < DEPTH; l++) {
        gemm_pk<<<dim3(NPAD_IN / 128, BT / 128), 256, SMEM_GEMM>>>(
            DINPROJ, DIM, phpk, pwin + (size_t)l * WIN_W, nullptr, pzx);
        pack_b<<<WOUT_W / 256, 256>>>(out_proj_w + (size_t)l * DIM * DINNER,
                                      pwout + (size_t)l * WOUT_W, DINNER, DIM);
        conv_silu_kernel<<<dim3(CONVCH / 256, BT), 256>>>(
            pzx, conv_w + (size_t)l * CONVCH * 4, conv_b + (size_t)l * CONVCH,
            pxbc);
        dt_kernel<<<(BT * NHEADS + 255) / 256, 256>>>(
            pzx, dt_bias + l * NHEADS, A_log + l * NHEADS, pdt, pdA);
        scan_kernel<<<(BB * NHEADS * HEADDIM * 32) / 256, 256>>>(
            pxbc, pzx, pdt, pdA, Dw + l * NHEADS, py);
        rmsnorm_kernel<<<BT, 256>>>(py, gnorm_w + (size_t)l * DINNER, DINNER);
        pack_a<<<YPK_B, 256>>>(py, pypk, DINNER);
        gemm_pk<<<dim3(DIM / 128, BT / 128), 256, SMEM_GEMM>>>(
            DIM, DINNER, pypk, pwout + (size_t)l * WOUT_W, ph, ph);
        pack_a<<<HPK_B, 256>>>(ph, phpk, DIM);
    }

    rmsnorm_kernel<<<BT, 256>>>(ph, final_norm_w, DIM);
    pack_a<<<HPK_B, 256>>>(ph, phpk, DIM);
    gemm_pk<<<dim3(VOCAB / 128, BT / 128), 256, SMEM_GEMM>>>(
        VOCAB, DIM, phpk, pemb, nullptr, out);
}

// round 8
// speedup vs baseline: 2.6773x; 1.1053x over previous
#include <cuda_runtime.h>
#include <cuda_fp16.h>
#include <math.h>
#include <stdint.h>

#define BB 2
#define TT 1024
#define DIM 1024
#define DEPTH 2
#define DSTATE 128
#define HEADDIM 64
#define NHEADS 32
#define DINNER 2048
#define CONVCH 2304
#define DINPROJ 4384
#define NPAD_IN 4480          // 35*128 padded in_proj rows
#define VOCAB 256
#define BT (BB*TT)

// ---------------- scratch (device globals; no allocations allowed) ----------
__device__ float g_h  [BT * DIM];
__device__ float g_zx [BT * DINPROJ];
__device__ float g_xbc[BT * CONVCH];
__device__ float g_dt [BT * NHEADS];
__device__ float g_dA [BT * NHEADS];
__device__ float g_y  [BT * DINNER];
// fragment-packed fp16 operands (each uint4 = one mma fragment / kstep pair)
//  A-pack: (M/16) * (K/16) * 32 uint4
//  B-pack: (N/8)  * (K/32) * 32 uint4
__device__ uint4 g_win_pk [DEPTH * (NPAD_IN/8) * (DIM/32)    * 32];
__device__ uint4 g_wout_pk[DEPTH * (DIM/8)     * (DINNER/32) * 32];
__device__ uint4 g_emb_pk [(VOCAB/8) * (DIM/32) * 32];
__device__ uint4 g_h_pk   [(BT/16) * (DIM/16)    * 32];
__device__ uint4 g_y_pk   [(BT/16) * (DINNER/16) * 32];

// ---------------- helpers ----------------
__device__ __forceinline__ uint32_t h2u(float lo, float hi) {
    __half2 h = __floats2half2_rn(lo, hi);
    return *(uint32_t*)&h;
}
__device__ __forceinline__ void mma_f16(float* c,
                                        uint32_t a0, uint32_t a1,
                                        uint32_t a2, uint32_t a3,
                                        uint32_t b0, uint32_t b1) {
    asm volatile(
        "mma.sync.aligned.m16n8k16.row.col.f32.f16.f16.f32 "
        "{%0,%1,%2,%3}, {%4,%5,%6,%7}, {%8,%9}, {%0,%1,%2,%3};"
        : "+f"(c[0]), "+f"(c[1]), "+f"(c[2]), "+f"(c[3])
        : "r"(a0), "r"(a1), "r"(a2), "r"(a3), "r"(b0), "r"(b1));
}
__device__ __forceinline__ void cpa16(uint32_t dst, const void* src) {
    asm volatile("cp.async.cg.shared.global [%0], [%1], 16;"
                 :: "r"(dst), "l"(src));
}
__device__ __forceinline__ uint32_t smem_u32(const void* p) {
    uint32_t a;
    asm("{ .reg .u64 t; cvta.to.shared.u64 t, %1; cvt.u32.u64 %0, t; }"
        : "=r"(a) : "l"(p));
    return a;
}

// ---------------- activation pack: fp32 [M,K] -> fp16 fragment order -------
// word idx = (mt*(K/16) + ks)*32 + lane ; g=lane>>2, q=lane&3
// word = {A(16mt+g, c:c+1), A(16mt+g+8, c:c+1), A(16mt+g, c+8:c+9),
//         A(16mt+g+8, c+8:c+9)}  with c = 16ks + 2q
__global__ void pack_a(const float* __restrict__ A, uint4* __restrict__ P,
                       int K) {
    int idx  = blockIdx.x * 256 + threadIdx.x;
    int lane = idx & 31;
    int t2   = idx >> 5;
    int ktn  = K >> 4;
    int ks   = t2 % ktn;
    int mt   = t2 / ktn;
    int g = lane >> 2, q = lane & 3;
    const float* r0 = A + (size_t)(mt * 16 + g) * K + ks * 16 + 2 * q;
    const float* r1 = r0 + (size_t)8 * K;
    float2 f0 = *(const float2*)r0;
    float2 f1 = *(const float2*)(r0 + 8);
    float2 f2 = *(const float2*)r1;
    float2 f3 = *(const float2*)(r1 + 8);
    P[idx] = make_uint4(h2u(f0.x, f0.y), h2u(f2.x, f2.y),
                        h2u(f1.x, f1.y), h2u(f3.x, f3.y));
}

// ---------------- weight pack: fp32 [Nsrc,K] -> fp16 fragment order --------
// word idx = (nt*(K/32) + kp)*32 + lane ; n = 8nt+g, base k = 32kp+2q
// word = {B(n,k:k+1), B(n,k+8:k+9), B(n,k+16:k+17), B(n,k+24:k+25)}
__global__ void pack_b(const float* __restrict__ B, uint4* __restrict__ P,
                       int K, int Nsrc) {
    int idx  = blockIdx.x * 256 + threadIdx.x;
    int lane = idx & 31;
    int t2   = idx >> 5;
    int kpn  = K >> 5;
    int kp   = t2 % kpn;
    int nt   = t2 / kpn;
    int g = lane >> 2, q = lane & 3;
    int n  = nt * 8 + g;
    uint4 w = make_uint4(0u, 0u, 0u, 0u);
    if (n < Nsrc) {
        const float* r = B + (size_t)n * K + kp * 32 + 2 * q;
        float2 f0 = *(const float2*)r;
        float2 f1 = *(const float2*)(r + 8);
        float2 f2 = *(const float2*)(r + 16);
        float2 f3 = *(const float2*)(r + 24);
        w = make_uint4(h2u(f0.x, f0.y), h2u(f1.x, f1.y),
                       h2u(f2.x, f2.y), h2u(f3.x, f3.y));
    }
    P[idx] = w;
}

// ---------------- embedding gather ----------------
__global__ void embed_kernel(const int* __restrict__ x,
                             const float* __restrict__ embed,
                             float* __restrict__ h) {
    int bt  = blockIdx.x;
    int tok = x[bt];
    const float4* src = (const float4*)(embed + (size_t)tok * DIM);
    ((float4*)(h + (size_t)bt * DIM))[threadIdx.x] = src[threadIdx.x];
}

// ---------------- packed fp16 GEMM: C[M,N] = A[M,K] B[N,K]^T (+Res) --------
// Tile 128x128, BK=64, 3-stage cp.async pipeline.
// stage = A 1024 uint4 (16KB) + B 1024 uint4 (16KB)
#define ST_W4     2048
#define SMEM_GEMM (3 * ST_W4 * 16)   // 96KB

__global__ void __launch_bounds__(256, 2)
gemm_pk(int N, int K,
        const uint4* __restrict__ Apk,
        const uint4* __restrict__ Bpk,
        const float* __restrict__ Res,
        float* __restrict__ C) {
    extern __shared__ uint4 sm4[];
    const uint32_t sbase = smem_u32(sm4);

    const int tid    = threadIdx.x;
    const int lane   = tid & 31;
    const int wid    = tid >> 5;
    const int warp_m = wid >> 2;       // 0..1
    const int warp_n = wid & 3;        // 0..3
    const int g      = lane >> 2;
    const int q      = lane & 3;
    const int row0   = blockIdx.y * 128;
    const int col0   = blockIdx.x * 128;
    const int ktn16  = K >> 4;
    const int kpn    = K >> 5;
    const int ktn    = K >> 6;         // BK=64 iterations

    // per-thread cp.async chunks: 4 A + 4 B per stage
    const uint4* asrc[4];
    const uint4* bsrc[4];
    uint32_t adst[4], bdst[4];
#pragma unroll
    for (int i = 0; i < 4; i++) {
        int ca = tid + 256 * i;                  // 0..1023
        int la = ca & 31, r = ca >> 5;
        int ksl = r & 3, mt = r >> 2;            // A: 8 mt x 4 ksteps
        asrc[i] = Apk + ((size_t)(row0 / 16 + mt) * ktn16 + ksl) * 32 + la;
        adst[i] = ca;
        int kpl = r & 1, nt = r >> 1;            // B: 16 nt x 2 kpairs
        bsrc[i] = Bpk + ((size_t)(col0 / 8 + nt) * kpn + kpl) * 32 + la;
        bdst[i] = 1024 + ca;
    }

    float acc[4][4][4];
#pragma unroll
    for (int i = 0; i < 4; i++)
#pragma unroll
        for (int j = 0; j < 4; j++)
#pragma unroll
            for (int r = 0; r < 4; r++) acc[i][j][r] = 0.f;

    // prologue: stages 0,1
#pragma unroll
    for (int p = 0; p < 2; p++) {
        uint32_t sb = sbase + p * ST_W4 * 16;
#pragma unroll
        for (int i = 0; i < 4; i++) cpa16(sb + adst[i] * 16, asrc[i] + p * 128);
#pragma unroll
        for (int i = 0; i < 4; i++) cpa16(sb + bdst[i] * 16, bsrc[i] + p * 64);
        asm volatile("cp.async.commit_group;");
    }

    for (int kt = 0; kt < ktn; kt++) {
        asm volatile("cp.async.wait_group 1;");
        __syncthreads();

        if (kt + 2 < ktn) {
            uint32_t sb = sbase + ((kt + 2) % 3) * ST_W4 * 16;
            size_t ao = (size_t)(kt + 2) * 128;
            size_t bo = (size_t)(kt + 2) * 64;
#pragma unroll
            for (int i = 0; i < 4; i++) cpa16(sb + adst[i] * 16, asrc[i] + ao);
#pragma unroll
            for (int i = 0; i < 4; i++) cpa16(sb + bdst[i] * 16, bsrc[i] + bo);
        }
        asm volatile("cp.async.commit_group;");

        const uint4* Ab = sm4 + (kt % 3) * ST_W4;
        const uint4* Bb = Ab + 1024;
#pragma unroll
        for (int kp = 0; kp < 2; kp++) {
            uint4 bw[4];
#pragma unroll
            for (int nt = 0; nt < 4; nt++)
                bw[nt] = Bb[((warp_n * 4 + nt) * 2 + kp) * 32 + lane];
#pragma unroll
            for (int hl = 0; hl < 2; hl++) {
                const int ks = kp * 2 + hl;
                uint4 af[4];
#pragma unroll
                for (int mt = 0; mt < 4; mt++)
                    af[mt] = Ab[((warp_m * 4 + mt) * 4 + ks) * 32 + lane];
#pragma unroll
                for (int mt = 0; mt < 4; mt++)
#pragma unroll
                    for (int nt = 0; nt < 4; nt++) {
                        uint32_t b0 = hl ? bw[nt].z : bw[nt].x;
                        uint32_t b1 = hl ? bw[nt].w : bw[nt].y;
                        mma_f16(acc[mt][nt], af[mt].x, af[mt].y, af[mt].z,
                                af[mt].w, b0, b1);
                    }
            }
        }
    }

    // epilogue: c0,c1 -> row g, cols 2q,2q+1 ; c2,c3 -> row g+8
#pragma unroll
    for (int mt = 0; mt < 4; mt++) {
        int r_lo = row0 + warp_m * 64 + mt * 16 + g;
#pragma unroll
        for (int nt = 0; nt < 4; nt++) {
            int c = col0 + warp_n * 32 + nt * 8 + q * 2;
            if (c < N) {
                float2 v0 = make_float2(acc[mt][nt][0], acc[mt][nt][1]);
                float2 v1 = make_float2(acc[mt][nt][2], acc[mt][nt][3]);
                size_t o0 = (size_t)r_lo * N + c;
                size_t o1 = (size_t)(r_lo + 8) * N + c;
                if (Res) {
                    float2 r0v = *(const float2*)(Res + o0);
                    float2 r1v = *(const float2*)(Res + o1);
                    v0.x += r0v.x; v0.y += r0v.y;
                    v1.x += r1v.x; v1.y += r1v.y;
                }
                *(float2*)(C + o0) = v0;
                *(float2*)(C + o1) = v1;
            }
        }
    }
}

// ---------------- causal depthwise conv (K=4) + SiLU ----------------
__global__ void conv_silu_kernel(const float* __restrict__ zx,
                                 const float* __restrict__ cw,
                                 const float* __restrict__ cb,
                                 float* __restrict__ xbc) {
    int c  = blockIdx.x * blockDim.x + threadIdx.x;
    int bt = blockIdx.y;
    int t  = bt % TT;
    int b  = bt / TT;
    float acc = cb[c];
#pragma unroll
    for (int k = 0; k < 4; k++) {
        int tt = t - 3 + k;
        if (tt >= 0)
            acc = fmaf(zx[(size_t)(b * TT + tt) * DINPROJ + DINNER + c],
                       cw[c * 4 + k], acc);
    }
    acc = acc / (1.f + expf(-acc));
    xbc[(size_t)bt * CONVCH + c] = acc;
}

// ---------------- dt = softplus(dt_raw + bias), dA = exp(-exp(Alog)*dt) -----
__global__ void dt_kernel(const float* __restrict__ zx,
                          const float* __restrict__ dtb,
                          const float* __restrict__ alog,
                          float* __restrict__ dt,
                          float* __restrict__ dA) {
    int idx = blockIdx.x * blockDim.x + threadIdx.x;
    if (idx >= BT * NHEADS) return;
    int h  = idx % NHEADS;
    int bt = idx / NHEADS;
    float v = zx[(size_t)bt * DINPROJ + (DINNER + CONVCH) + h] + dtb[h];
    float d = (v > 20.f) ? v : log1pf(expf(v));
    dt[idx] = d;
    dA[idx] = expf(-expf(alog[h]) * d);
}

// ---------------- sequential SSM scan: one warp per (b, head, p) ------------
__global__ void __launch_bounds__(256)
scan_kernel(const float* __restrict__ xbc,
            const float* __restrict__ zx,
            const float* __restrict__ dt,
            const float* __restrict__ dA,
            const float* __restrict__ Dw,
            float* __restrict__ y) {
    int gtid = blockIdx.x * blockDim.x + threadIdx.x;
    int w    = gtid >> 5;
    int lane = gtid & 31;
    int b  = w >> 11;
    int hp = w & 2047;
    int h  = hp >> 6;
    int p  = hp & 63;

    float4 s = make_float4(0.f, 0.f, 0.f, 0.f);
    float  Dh = Dw[h];
    const float* xb = xbc + (size_t)b * TT * CONVCH;
    const float* zb = zx  + (size_t)b * TT * DINPROJ;
    const int n0 = lane * 4;

#pragma unroll 2
    for (int t = 0; t < TT; t++) {
        const float* row = xb + (size_t)t * CONVCH;
        int bth = (b * TT + t) * NHEADS + h;
        float da  = dA[bth];
        float dtv = dt[bth];
        float xv  = row[h * 64 + p];
        float4 Bv = *(const float4*)(row + DINNER + n0);
        float4 Cv = *(const float4*)(row + DINNER + DSTATE + n0);
        float coef = dtv * xv;
        s.x = fmaf(da, s.x, coef * Bv.x);
        s.y = fmaf(da, s.y, coef * Bv.y);
        s.z = fmaf(da, s.z, coef * Bv.z);
        s.w = fmaf(da, s.w, coef * Bv.w);
        float part = s.x * Cv.x + s.y * Cv.y + s.z * Cv.z + s.w * Cv.w;
#pragma unroll
        for (int o = 16; o; o >>= 1)
            part += __shfl_xor_sync(0xFFFFFFFFu, part, o);
        if (lane == 0) {
            float yo = part + Dh * xv;
            float z  = zb[(size_t)t * DINPROJ + h * 64 + p];
            yo *= z / (1.f + expf(-z));
            y[(size_t)(b * TT + t) * DINNER + h * 64 + p] = yo;
        }
    }
}

// ---------------- RMSNorm (in-place), one block per row ----------------
__global__ void rmsnorm_kernel(float* __restrict__ data,
                               const float* __restrict__ w, int n) {
    float* r = data + (size_t)blockIdx.x * n;
    float ss = 0.f;
    for (int i = threadIdx.x; i < n; i += blockDim.x) {
        float v = r[i];
        ss = fmaf(v, v, ss);
    }
#pragma unroll
    for (int o = 16; o; o >>= 1) ss += __shfl_xor_sync(0xFFFFFFFFu, ss, o);
    __shared__ float sh[9];
    int wid = threadIdx.x >> 5, lane = threadIdx.x & 31;
    if (lane == 0) sh[wid] = ss;
    __syncthreads();
    if (wid == 0) {
        float v = (lane < 8) ? sh[lane] : 0.f;
#pragma unroll
        for (int o = 16; o; o >>= 1) v += __shfl_xor_sync(0xFFFFFFFFu, v, o);
        if (lane == 0) sh[8] = rsqrtf(v / n + 1e-5f);
    }
    __syncthreads();
    float sc = sh[8];
    for (int i = threadIdx.x; i < n; i += blockDim.x)
        r[i] = r[i] * sc * w[i];
}

// ---------------- launcher ----------------
extern "C" void kernel_launch(void* const* d_in, const int* in_sizes, int n_in,
                              void* d_out, int out_size) {
    const int*   x            = (const int*)  d_in[0];
    const float* embed        = (const float*)d_in[1];
    const float* in_proj_w    = (const float*)d_in[2];
    const float* conv_w       = (const float*)d_in[3];
    const float* conv_b       = (const float*)d_in[4];
    const float* dt_bias      = (const float*)d_in[5];
    const float* A_log        = (const float*)d_in[6];
    const float* Dw           = (const float*)d_in[7];
    const float* gnorm_w      = (const float*)d_in[8];
    const float* out_proj_w   = (const float*)d_in[9];
    const float* final_norm_w = (const float*)d_in[10];
    float* out = (float*)d_out;

    float *ph, *pzx, *pxbc, *pdt, *pdA, *py;
    uint4 *pwin, *pwout, *pemb, *phpk, *pypk;
    cudaGetSymbolAddress((void**)&ph,    g_h);
    cudaGetSymbolAddress((void**)&pzx,   g_zx);
    cudaGetSymbolAddress((void**)&pxbc,  g_xbc);
    cudaGetSymbolAddress((void**)&pdt,   g_dt);
    cudaGetSymbolAddress((void**)&pdA,   g_dA);
    cudaGetSymbolAddress((void**)&py,    g_y);
    cudaGetSymbolAddress((void**)&pwin,  g_win_pk);
    cudaGetSymbolAddress((void**)&pwout, g_wout_pk);
    cudaGetSymbolAddress((void**)&pemb,  g_emb_pk);
    cudaGetSymbolAddress((void**)&phpk,  g_h_pk);
    cudaGetSymbolAddress((void**)&pypk,  g_y_pk);

    cudaFuncSetAttribute(gemm_pk, cudaFuncAttributeMaxDynamicSharedMemorySize,
                         SMEM_GEMM);

    const int WIN_W  = (NPAD_IN / 8) * (DIM / 32) * 32;     // words per layer
    const int WOUT_W = (DIM / 8) * (DINNER / 32) * 32;
    const int EMB_W  = (VOCAB / 8) * (DIM / 32) * 32;
    const int HPK_B  = (BT / 16) * (DIM / 16) * 32 / 256;
    const int YPK_B  = (BT / 16) * (DINNER / 16) * 32 / 256;

    // launches 1-3, then launch 4 = in_proj GEMM (ncu sample window)
    pack_b<<<WIN_W / 256, 256>>>(in_proj_w, pwin, DIM, DINPROJ);
    embed_kernel<<<BT, 256>>>(x, embed, ph);
    pack_a<<<HPK_B, 256>>>(ph, phpk, DIM);

    for (int l = 0; l < DEPTH; l++) {
        gemm_pk<<<dim3(NPAD_IN / 128, BT / 128), 256, SMEM_GEMM>>>(
            DINPROJ, DIM, phpk, pwin + (size_t)l * WIN_W, nullptr, pzx);
        pack_b<<<WOUT_W / 256, 256>>>(out_proj_w + (size_t)l * DIM * DINNER,
                                      pwout + (size_t)l * WOUT_W, DINNER, DIM);
        if (l + 1 < DEPTH)
            pack_b<<<WIN_W / 256, 256>>>(in_proj_w + (size_t)(l+1) * DINPROJ * DIM,
                                         pwin + (size_t)(l+1) * WIN_W, DIM,
                                         DINPROJ);
        conv_silu_kernel<<<dim3(CONVCH / 256, BT), 256>>>(
            pzx, conv_w + (size_t)l * CONVCH * 4, conv_b + (size_t)l * CONVCH,
            pxbc);
        dt_kernel<<<(BT * NHEADS + 255) / 256, 256>>>(
            pzx, dt_bias + l * NHEADS, A_log + l * NHEADS, pdt, pdA);
        scan_kernel<<<(BB * NHEADS * HEADDIM * 32) / 256, 256>>>(
            pxbc, pzx, pdt, pdA, Dw + l * NHEADS, py);
        rmsnorm_kernel<<<BT, 256>>>(py, gnorm_w + (size_t)l * DINNER, DINNER);
        pack_a<<<YPK_B, 256>>>(py, pypk, DINNER);
        gemm_pk<<<dim3(DIM / 128, BT / 128), 256, SMEM_GEMM>>>(
            DIM, DINNER, pypk, pwout + (size_t)l * WOUT_W, ph, ph);
        pack_a<<<HPK_B, 256>>>(ph, phpk, DIM);
    }

    rmsnorm_kernel<<<BT, 256>>>(ph, final_norm_w, DIM);
    pack_a<<<HPK_B, 256>>>(ph, phpk, DIM);
    pack_b<<<EMB_W / 256, 256>>>(embed, pemb, DIM, VOCAB);
    gemm_pk<<<dim3(VOCAB / 128, BT / 128), 256, SMEM_GEMM>>>(
        VOCAB, DIM, phpk, pemb, nullptr, out);
}

// round 9
// speedup vs baseline: 5.6562x; 2.1126x over previous
#include <cuda_runtime.h>
#include <cuda_fp16.h>
#include <math.h>
#include <stdint.h>

#define BB 2
#define TT 1024
#define DIM 1024
#define DEPTH 2
#define DSTATE 128
#define HEADDIM 64
#define NHEADS 32
#define DINNER 2048
#define CONVCH 2304
#define DINPROJ 4384
#define NPAD_IN 4480          // 35*128 padded in_proj rows
#define VOCAB 256
#define BT (BB*TT)

// ---------------- scratch (device globals; no allocations allowed) ----------
__device__ float g_h  [BT * DIM];
__device__ float g_zx [BT * DINPROJ];
__device__ float g_xbc[BT * CONVCH];
__device__ float g_y  [BT * DINNER];
__device__ float g_yp0[BT * DINNER];    // scan partials, n-half 0
__device__ float g_yp1[BT * DINNER];    // scan partials, n-half 1
// fragment-packed fp16 operands
__device__ uint4 g_win_pk [DEPTH * (NPAD_IN/8) * (DIM/32)    * 32];
__device__ uint4 g_wout_pk[DEPTH * (DIM/8)     * (DINNER/32) * 32];
__device__ uint4 g_emb_pk [(VOCAB/8) * (DIM/32) * 32];
__device__ uint4 g_h_pk   [(BT/16) * (DIM/16)    * 32];
__device__ uint4 g_y_pk   [(BT/16) * (DINNER/16) * 32];

// ---------------- helpers ----------------
__device__ __forceinline__ uint32_t h2u(float lo, float hi) {
    __half2 h = __floats2half2_rn(lo, hi);
    return *(uint32_t*)&h;
}
__device__ __forceinline__ void mma_f16(float* c,
                                        uint32_t a0, uint32_t a1,
                                        uint32_t a2, uint32_t a3,
                                        uint32_t b0, uint32_t b1) {
    asm volatile(
        "mma.sync.aligned.m16n8k16.row.col.f32.f16.f16.f32 "
        "{%0,%1,%2,%3}, {%4,%5,%6,%7}, {%8,%9}, {%0,%1,%2,%3};"
        : "+f"(c[0]), "+f"(c[1]), "+f"(c[2]), "+f"(c[3])
        : "r"(a0), "r"(a1), "r"(a2), "r"(a3), "r"(b0), "r"(b1));
}
__device__ __forceinline__ void cpa16(uint32_t dst, const void* src) {
    asm volatile("cp.async.cg.shared.global [%0], [%1], 16;"
                 :: "r"(dst), "l"(src));
}
__device__ __forceinline__ uint32_t smem_u32(const void* p) {
    uint32_t a;
    asm("{ .reg .u64 t; cvta.to.shared.u64 t, %1; cvt.u32.u64 %0, t; }"
        : "=r"(a) : "l"(p));
    return a;
}

// ---------------- activation pack: fp32 [M,K] -> fp16 fragment order -------
__global__ void pack_a(const float* __restrict__ A, uint4* __restrict__ P,
                       int K) {
    int idx  = blockIdx.x * 256 + threadIdx.x;
    int lane = idx & 31;
    int t2   = idx >> 5;
    int ktn  = K >> 4;
    int ks   = t2 % ktn;
    int mt   = t2 / ktn;
    int g = lane >> 2, q = lane & 3;
    const float* r0 = A + (size_t)(mt * 16 + g) * K + ks * 16 + 2 * q;
    const float* r1 = r0 + (size_t)8 * K;
    float2 f0 = *(const float2*)r0;
    float2 f1 = *(const float2*)(r0 + 8);
    float2 f2 = *(const float2*)r1;
    float2 f3 = *(const float2*)(r1 + 8);
    P[idx] = make_uint4(h2u(f0.x, f0.y), h2u(f2.x, f2.y),
                        h2u(f1.x, f1.y), h2u(f3.x, f3.y));
}

// ---------------- weight pack: fp32 [Nsrc,K] -> fp16 fragment order --------
__global__ void pack_b(const float* __restrict__ B, uint4* __restrict__ P,
                       int K, int Nsrc) {
    int idx  = blockIdx.x * 256 + threadIdx.x;
    int lane = idx & 31;
    int t2   = idx >> 5;
    int kpn  = K >> 5;
    int kp   = t2 % kpn;
    int nt   = t2 / kpn;
    int g = lane >> 2, q = lane & 3;
    int n  = nt * 8 + g;
    uint4 w = make_uint4(0u, 0u, 0u, 0u);
    if (n < Nsrc) {
        const float* r = B + (size_t)n * K + kp * 32 + 2 * q;
        float2 f0 = *(const float2*)r;
        float2 f1 = *(const float2*)(r + 8);
        float2 f2 = *(const float2*)(r + 16);
        float2 f3 = *(const float2*)(r + 24);
        w = make_uint4(h2u(f0.x, f0.y), h2u(f1.x, f1.y),
                       h2u(f2.x, f2.y), h2u(f3.x, f3.y));
    }
    P[idx] = w;
}

// ---------------- embedding gather ----------------
__global__ void embed_kernel(const int* __restrict__ x,
                             const float* __restrict__ embed,
                             float* __restrict__ h) {
    int bt  = blockIdx.x;
    int tok = x[bt];
    const float4* src = (const float4*)(embed + (size_t)tok * DIM);
    ((float4*)(h + (size_t)bt * DIM))[threadIdx.x] = src[threadIdx.x];
}

// ---------------- packed fp16 GEMM: C[M,N] = A[M,K] B[N,K]^T (+Res) --------
#define ST_W4     2048
#define SMEM_GEMM (3 * ST_W4 * 16)   // 96KB

__global__ void __launch_bounds__(256, 2)
gemm_pk(int N, int K,
        const uint4* __restrict__ Apk,
        const uint4* __restrict__ Bpk,
        const float* __restrict__ Res,
        float* __restrict__ C) {
    extern __shared__ uint4 sm4[];
    const uint32_t sbase = smem_u32(sm4);

    const int tid    = threadIdx.x;
    const int lane   = tid & 31;
    const int wid    = tid >> 5;
    const int warp_m = wid >> 2;
    const int warp_n = wid & 3;
    const int g      = lane >> 2;
    const int q      = lane & 3;
    const int row0   = blockIdx.y * 128;
    const int col0   = blockIdx.x * 128;
    const int ktn16  = K >> 4;
    const int kpn    = K >> 5;
    const int ktn    = K >> 6;

    const uint4* asrc[4];
    const uint4* bsrc[4];
    uint32_t adst[4], bdst[4];
#pragma unroll
    for (int i = 0; i < 4; i++) {
        int ca = tid + 256 * i;
        int la = ca & 31, r = ca >> 5;
        int ksl = r & 3, mt = r >> 2;
        asrc[i] = Apk + ((size_t)(row0 / 16 + mt) * ktn16 + ksl) * 32 + la;
        adst[i] = ca;
        int kpl = r & 1, nt = r >> 1;
        bsrc[i] = Bpk + ((size_t)(col0 / 8 + nt) * kpn + kpl) * 32 + la;
        bdst[i] = 1024 + ca;
    }

    float acc[4][4][4];
#pragma unroll
    for (int i = 0; i < 4; i++)
#pragma unroll
        for (int j = 0; j < 4; j++)
#pragma unroll
            for (int r = 0; r < 4; r++) acc[i][j][r] = 0.f;

#pragma unroll
    for (int p = 0; p < 2; p++) {
        uint32_t sb = sbase + p * ST_W4 * 16;
#pragma unroll
        for (int i = 0; i < 4; i++) cpa16(sb + adst[i] * 16, asrc[i] + p * 128);
#pragma unroll
        for (int i = 0; i < 4; i++) cpa16(sb + bdst[i] * 16, bsrc[i] + p * 64);
        asm volatile("cp.async.commit_group;");
    }

    for (int kt = 0; kt < ktn; kt++) {
        asm volatile("cp.async.wait_group 1;");
        __syncthreads();

        if (kt + 2 < ktn) {
            uint32_t sb = sbase + ((kt + 2) % 3) * ST_W4 * 16;
            size_t ao = (size_t)(kt + 2) * 128;
            size_t bo = (size_t)(kt + 2) * 64;
#pragma unroll
            for (int i = 0; i < 4; i++) cpa16(sb + adst[i] * 16, asrc[i] + ao);
#pragma unroll
            for (int i = 0; i < 4; i++) cpa16(sb + bdst[i] * 16, bsrc[i] + bo);
        }
        asm volatile("cp.async.commit_group;");

        const uint4* Ab = sm4 + (kt % 3) * ST_W4;
        const uint4* Bb = Ab + 1024;
#pragma unroll
        for (int kp = 0; kp < 2; kp++) {
            uint4 bw[4];
#pragma unroll
            for (int nt = 0; nt < 4; nt++)
                bw[nt] = Bb[((warp_n * 4 + nt) * 2 + kp) * 32 + lane];
#pragma unroll
            for (int hl = 0; hl < 2; hl++) {
                const int ks = kp * 2 + hl;
                uint4 af[4];
#pragma unroll
                for (int mt = 0; mt < 4; mt++)
                    af[mt] = Ab[((warp_m * 4 + mt) * 4 + ks) * 32 + lane];
#pragma unroll
                for (int mt = 0; mt < 4; mt++)
#pragma unroll
                    for (int nt = 0; nt < 4; nt++) {
                        uint32_t b0 = hl ? bw[nt].z : bw[nt].x;
                        uint32_t b1 = hl ? bw[nt].w : bw[nt].y;
                        mma_f16(acc[mt][nt], af[mt].x, af[mt].y, af[mt].z,
                                af[mt].w, b0, b1);
                    }
            }
        }
    }

#pragma unroll
    for (int mt = 0; mt < 4; mt++) {
        int r_lo = row0 + warp_m * 64 + mt * 16 + g;
#pragma unroll
        for (int nt = 0; nt < 4; nt++) {
            int c = col0 + warp_n * 32 + nt * 8 + q * 2;
            if (c < N) {
                float2 v0 = make_float2(acc[mt][nt][0], acc[mt][nt][1]);
                float2 v1 = make_float2(acc[mt][nt][2], acc[mt][nt][3]);
                size_t o0 = (size_t)r_lo * N + c;
                size_t o1 = (size_t)(r_lo + 8) * N + c;
                if (Res) {
                    float2 r0v = *(const float2*)(Res + o0);
                    float2 r1v = *(const float2*)(Res + o1);
                    v0.x += r0v.x; v0.y += r0v.y;
                    v1.x += r1v.x; v1.y += r1v.y;
                }
                *(float2*)(C + o0) = v0;
                *(float2*)(C + o1) = v1;
            }
        }
    }
}

// ---------------- causal depthwise conv (K=4) + SiLU ----------------
__global__ void conv_silu_kernel(const float* __restrict__ zx,
                                 const float* __restrict__ cw,
                                 const float* __restrict__ cb,
                                 float* __restrict__ xbc) {
    int c  = blockIdx.x * blockDim.x + threadIdx.x;
    int bt = blockIdx.y;
    int t  = bt % TT;
    int b  = bt / TT;
    float acc = cb[c];
#pragma unroll
    for (int k = 0; k < 4; k++) {
        int tt = t - 3 + k;
        if (tt >= 0)
            acc = fmaf(zx[(size_t)(b * TT + tt) * DINPROJ + DINNER + c],
                       cw[c * 4 + k], acc);
    }
    acc = acc / (1.f + expf(-acc));
    xbc[(size_t)bt * CONVCH + c] = acc;
}

// ---------------- SSM scan v2: CTA per (b, head, n-half) -------------------
// 256 threads: thread = (p in 64, nq in 4), owns s[p][nq*16 .. nq*16+15].
// B/C/x staged per 8-step chunk into smem (bank-swizzled), dt/dA computed
// inline from zx. Dot partials reduced over nq lanes (2 shfl), n-half
// partials combined later in rmsgate.
#define SCH 8
__global__ void __launch_bounds__(256)
scan2_kernel(const float* __restrict__ xbc,
             const float* __restrict__ zx,
             const float* __restrict__ dtb,
             const float* __restrict__ alog,
             float* __restrict__ yp0,
             float* __restrict__ yp1) {
    __shared__ __align__(16) float Bs[SCH][64];
    __shared__ __align__(16) float Cs[SCH][64];
    __shared__ __align__(16) float Xs[SCH][64];
    __shared__ float As[SCH], Ds[SCH];

    const int tid  = threadIdx.x;
    const int nh   = blockIdx.x;     // n-half
    const int h    = blockIdx.y;
    const int b    = blockIdx.z;
    const int wid  = tid >> 5;
    const int lane = tid & 31;
    const int pl   = lane >> 2;
    const int nq   = lane & 3;
    const int p    = wid * 8 + pl;

    float s[16];
#pragma unroll
    for (int i = 0; i < 16; i++) s[i] = 0.f;

    const float* xrow = xbc + (size_t)b * TT * CONVCH;
    const int xoff = h * 64;
    const int boff = DINNER + nh * 64;
    const int coff = DINNER + DSTATE + nh * 64;
    const float dtbv = dtb[h];
    const float aexp = expf(alog[h]);
    float* yout = (nh == 0 ? yp0 : yp1) + (size_t)b * TT * DINNER + h * 64;

    for (int t0 = 0; t0 < TT; t0 += SCH) {
        __syncthreads();
        // stage B/C/x: 384 float4 chunks, bank-swizzled per 16-float group
        for (int j = tid; j < 384; j += 256) {
            int arr = j >> 7;            // 0=B 1=C 2=X
            int rem = j & 127;
            int tt  = rem >> 4;
            int q4  = rem & 15;
            const float* base = xrow + (size_t)(t0 + tt) * CONVCH;
            const float4* src;
            float* dst;
            if (arr == 0) {
                src = (const float4*)(base + boff) + q4;
                dst = &Bs[tt][((q4 & 3) << 4) + ((q4 >> 2) << 2)];
            } else if (arr == 1) {
                src = (const float4*)(base + coff) + q4;
                dst = &Cs[tt][((q4 & 3) << 4) + ((q4 >> 2) << 2)];
            } else {
                src = (const float4*)(base + xoff) + q4;
                dst = &Xs[tt][q4 << 2];
            }
            *(float4*)dst = *src;
        }
        if (tid < SCH) {
            size_t bt = (size_t)(b * TT + t0 + tid);
            float v = zx[bt * DINPROJ + DINNER + CONVCH + h] + dtbv;
            float d = (v > 20.f) ? v : log1pf(expf(v));
            Ds[tid] = d;
            As[tid] = expf(-aexp * d);
        }
        __syncthreads();

#pragma unroll
        for (int tt = 0; tt < SCH; tt++) {
            const float da   = As[tt];
            const float coef = Ds[tt] * Xs[tt][p];
            // swizzled fragment pointers: float4 index = i4*4 + nq
            const float4* B4 = (const float4*)&Bs[tt][0];
            const float4* C4 = (const float4*)&Cs[tt][0];
            float part = 0.f;
#pragma unroll
            for (int i4 = 0; i4 < 4; i4++) {
                float4 bv = B4[i4 * 4 + nq];
                float4 cv = C4[i4 * 4 + nq];
                float* sp = s + i4 * 4;
                sp[0] = fmaf(da, sp[0], coef * bv.x);
                sp[1] = fmaf(da, sp[1], coef * bv.y);
                sp[2] = fmaf(da, sp[2], coef * bv.z);
                sp[3] = fmaf(da, sp[3], coef * bv.w);
                part = fmaf(sp[0], cv.x, part);
                part = fmaf(sp[1], cv.y, part);
                part = fmaf(sp[2], cv.z, part);
                part = fmaf(sp[3], cv.w, part);
            }
            part += __shfl_xor_sync(0xFFFFFFFFu, part, 1);
            part += __shfl_xor_sync(0xFFFFFFFFu, part, 2);
            if (nq == 0)
                yout[(size_t)(t0 + tt) * DINNER + p] = part;
        }
    }
}

// ---------------- fused gate + RMSNorm: one block per (b,t) row ------------
// v = (y0 + y1 + D[h]*x) * silu(z); out = v * rsqrt(mean(v^2)+eps) * w
__global__ void __launch_bounds__(256)
rmsgate_kernel(const float* __restrict__ y0,
               const float* __restrict__ y1,
               const float* __restrict__ xbc,
               const float* __restrict__ zx,
               const float* __restrict__ Dw,
               const float* __restrict__ w,
               float* __restrict__ out) {
    __shared__ float vc[DINNER];
    __shared__ float sh[9];
    const int bt = blockIdx.x;
    const float* y0r = y0 + (size_t)bt * DINNER;
    const float* y1r = y1 + (size_t)bt * DINNER;
    const float* xr  = xbc + (size_t)bt * CONVCH;
    const float* zr  = zx + (size_t)bt * DINPROJ;
    float* outr = out + (size_t)bt * DINNER;

    float ss = 0.f;
    for (int i = threadIdx.x; i < DINNER; i += 256) {
        float yv = y0r[i] + y1r[i] + Dw[i >> 6] * xr[i];
        float z  = zr[i];
        float v  = yv * (z / (1.f + expf(-z)));
        vc[i] = v;
        ss = fmaf(v, v, ss);
    }
#pragma unroll
    for (int o = 16; o; o >>= 1) ss += __shfl_xor_sync(0xFFFFFFFFu, ss, o);
    int wid = threadIdx.x >> 5, lane = threadIdx.x & 31;
    if (lane == 0) sh[wid] = ss;
    __syncthreads();
    if (wid == 0) {
        float v = (lane < 8) ? sh[lane] : 0.f;
#pragma unroll
        for (int o = 16; o; o >>= 1) v += __shfl_xor_sync(0xFFFFFFFFu, v, o);
        if (lane == 0) sh[8] = rsqrtf(v / DINNER + 1e-5f);
    }
    __syncthreads();
    float sc = sh[8];
    for (int i = threadIdx.x; i < DINNER; i += 256)
        outr[i] = vc[i] * sc * w[i];
}

// ---------------- plain RMSNorm (final norm) ----------------
__global__ void rmsnorm_kernel(float* __restrict__ data,
                               const float* __restrict__ w, int n) {
    float* r = data + (size_t)blockIdx.x * n;
    float ss = 0.f;
    for (int i = threadIdx.x; i < n; i += blockDim.x) {
        float v = r[i];
        ss = fmaf(v, v, ss);
    }
#pragma unroll
    for (int o = 16; o; o >>= 1) ss += __shfl_xor_sync(0xFFFFFFFFu, ss, o);
    __shared__ float sh[9];
    int wid = threadIdx.x >> 5, lane = threadIdx.x & 31;
    if (lane == 0) sh[wid] = ss;
    __syncthreads();
    if (wid == 0) {
        float v = (lane < 8) ? sh[lane] : 0.f;
#pragma unroll
        for (int o = 16; o; o >>= 1) v += __shfl_xor_sync(0xFFFFFFFFu, v, o);
        if (lane == 0) sh[8] = rsqrtf(v / n + 1e-5f);
    }
    __syncthreads();
    float sc = sh[8];
    for (int i = threadIdx.x; i < n; i += blockDim.x)
        r[i] = r[i] * sc * w[i];
}

// ---------------- launcher ----------------
extern "C" void kernel_launch(void* const* d_in, const int* in_sizes, int n_in,
                              void* d_out, int out_size) {
    const int*   x            = (const int*)  d_in[0];
    const float* embed        = (const float*)d_in[1];
    const float* in_proj_w    = (const float*)d_in[2];
    const float* conv_w       = (const float*)d_in[3];
    const float* conv_b       = (const float*)d_in[4];
    const float* dt_bias      = (const float*)d_in[5];
    const float* A_log        = (const float*)d_in[6];
    const float* Dw           = (const float*)d_in[7];
    const float* gnorm_w      = (const float*)d_in[8];
    const float* out_proj_w   = (const float*)d_in[9];
    const float* final_norm_w = (const float*)d_in[10];
    float* out = (float*)d_out;

    float *ph, *pzx, *pxbc, *py, *pyp0, *pyp1;
    uint4 *pwin, *pwout, *pemb, *phpk, *pypk;
    cudaGetSymbolAddress((void**)&ph,    g_h);
    cudaGetSymbolAddress((void**)&pzx,   g_zx);
    cudaGetSymbolAddress((void**)&pxbc,  g_xbc);
    cudaGetSymbolAddress((void**)&py,    g_y);
    cudaGetSymbolAddress((void**)&pyp0,  g_yp0);
    cudaGetSymbolAddress((void**)&pyp1,  g_yp1);
    cudaGetSymbolAddress((void**)&pwin,  g_win_pk);
    cudaGetSymbolAddress((void**)&pwout, g_wout_pk);
    cudaGetSymbolAddress((void**)&pemb,  g_emb_pk);
    cudaGetSymbolAddress((void**)&phpk,  g_h_pk);
    cudaGetSymbolAddress((void**)&pypk,  g_y_pk);

    cudaFuncSetAttribute(gemm_pk, cudaFuncAttributeMaxDynamicSharedMemorySize,
                         SMEM_GEMM);

    const int WIN_W  = (NPAD_IN / 8) * (DIM / 32) * 32;
    const int WOUT_W = (DIM / 8) * (DINNER / 32) * 32;
    const int EMB_W  = (VOCAB / 8) * (DIM / 32) * 32;
    const int HPK_B  = (BT / 16) * (DIM / 16) * 32 / 256;
    const int YPK_B  = (BT / 16) * (DINNER / 16) * 32 / 256;

    // launches 1-5; launch 6 = scan2 of layer 0 (ncu -s 5 -c 1 window)
    pack_b<<<WIN_W / 256, 256>>>(in_proj_w, pwin, DIM, DINPROJ);
    embed_kernel<<<BT, 256>>>(x, embed, ph);
    pack_a<<<HPK_B, 256>>>(ph, phpk, DIM);

    for (int l = 0; l < DEPTH; l++) {
        gemm_pk<<<dim3(NPAD_IN / 128, BT / 128), 256, SMEM_GEMM>>>(
            DINPROJ, DIM, phpk, pwin + (size_t)l * WIN_W, nullptr, pzx);
        conv_silu_kernel<<<dim3(CONVCH / 256, BT), 256>>>(
            pzx, conv_w + (size_t)l * CONVCH * 4, conv_b + (size_t)l * CONVCH,
            pxbc);
        scan2_kernel<<<dim3(2, NHEADS, BB), 256>>>(
            pxbc, pzx, dt_bias + l * NHEADS, A_log + l * NHEADS, pyp0, pyp1);
        pack_b<<<WOUT_W / 256, 256>>>(out_proj_w + (size_t)l * DIM * DINNER,
                                      pwout + (size_t)l * WOUT_W, DINNER, DIM);
        if (l + 1 < DEPTH)
            pack_b<<<WIN_W / 256, 256>>>(
                in_proj_w + (size_t)(l + 1) * DINPROJ * DIM,
                pwin + (size_t)(l + 1) * WIN_W, DIM, DINPROJ);
        rmsgate_kernel<<<BT, 256>>>(pyp0, pyp1, pxbc, pzx, Dw + l * NHEADS,
                                    gnorm_w + (size_t)l * DINNER, py);
        pack_a<<<YPK_B, 256>>>(py, pypk, DINNER);
        gemm_pk<<<dim3(DIM / 128, BT / 128), 256, SMEM_GEMM>>>(
            DIM, DINNER, pypk, pwout + (size_t)l * WOUT_W, ph, ph);
        pack_a<<<HPK_B, 256>>>(ph, phpk, DIM);
    }

    rmsnorm_kernel<<<BT, 256>>>(ph, final_norm_w, DIM);
    pack_a<<<HPK_B, 256>>>(ph, phpk, DIM);
    pack_b<<<EMB_W / 256, 256>>>(embed, pemb, DIM, VOCAB);
    gemm_pk<<<dim3(VOCAB / 128, BT / 128), 256, SMEM_GEMM>>>(
        VOCAB, DIM, phpk, pemb, nullptr, out);
}

// round 10
// speedup vs baseline: 5.7831x; 1.0224x over previous
#include <cuda_runtime.h>
#include <cuda_fp16.h>
#include <math.h>
#include <stdint.h>

#define BB 2
#define TT 1024
#define DIM 1024
#define DEPTH 2
#define DSTATE 128
#define HEADDIM 64
#define NHEADS 32
#define DINNER 2048
#define CONVCH 2304
#define DINPROJ 4384
#define NPAD_IN 4480          // 35*128 padded in_proj rows
#define VOCAB 256
#define BT (BB*TT)

// ---------------- scratch (device globals; no allocations allowed) ----------
__device__ float g_h  [BT * DIM];
__device__ float g_zx [BT * DINPROJ];
__device__ float g_yp [4 * BT * DINNER];   // scan partials, 4 n-quarters
// fragment-packed fp16 operands
__device__ uint4 g_win_pk [DEPTH * (NPAD_IN/8) * (DIM/32)    * 32];
__device__ uint4 g_wout_pk[DEPTH * (DIM/8)     * (DINNER/32) * 32];
__device__ uint4 g_emb_pk [(VOCAB/8) * (DIM/32) * 32];
__device__ uint4 g_h_pk   [(BT/16) * (DIM/16)    * 32];
__device__ uint4 g_y_pk   [(BT/16) * (DINNER/16) * 32];

// ---------------- helpers ----------------
__device__ __forceinline__ uint32_t h2u(float lo, float hi) {
    __half2 h = __floats2half2_rn(lo, hi);
    return *(uint32_t*)&h;
}
// fragment-packed store of pair (m, c), (m, c+1); c even. Inverse of pack_a.
__device__ __forceinline__ void pk_store(uint32_t* __restrict__ P, int K,
                                         int m, int c, float lo, float hi) {
    int word = (((m >> 4) * (K >> 4) + (c >> 4)) << 5) + ((m & 7) << 2) +
               ((c >> 1) & 3);
    P[(word << 2) + ((m >> 3) & 1) + (((c >> 3) & 1) << 1)] = h2u(lo, hi);
}
__device__ __forceinline__ void mma_f16(float* c,
                                        uint32_t a0, uint32_t a1,
                                        uint32_t a2, uint32_t a3,
                                        uint32_t b0, uint32_t b1) {
    asm volatile(
        "mma.sync.aligned.m16n8k16.row.col.f32.f16.f16.f32 "
        "{%0,%1,%2,%3}, {%4,%5,%6,%7}, {%8,%9}, {%0,%1,%2,%3};"
        : "+f"(c[0]), "+f"(c[1]), "+f"(c[2]), "+f"(c[3])
        : "r"(a0), "r"(a1), "r"(a2), "r"(a3), "r"(b0), "r"(b1));
}
__device__ __forceinline__ void cpa16(uint32_t dst, const void* src) {
    asm volatile("cp.async.cg.shared.global [%0], [%1], 16;"
                 :: "r"(dst), "l"(src));
}
__device__ __forceinline__ uint32_t smem_u32(const void* p) {
    uint32_t a;
    asm("{ .reg .u64 t; cvta.to.shared.u64 t, %1; cvt.u32.u64 %0, t; }"
        : "=r"(a) : "l"(p));
    return a;
}

// ---------------- weight pack: fp32 [Nsrc,K] -> fp16 fragment order --------
__global__ void pack_b(const float* __restrict__ B, uint4* __restrict__ P,
                       int K, int Nsrc) {
    int idx  = blockIdx.x * 256 + threadIdx.x;
    int lane = idx & 31;
    int t2   = idx >> 5;
    int kpn  = K >> 5;
    int kp   = t2 % kpn;
    int nt   = t2 / kpn;
    int g = lane >> 2, q = lane & 3;
    int n  = nt * 8 + g;
    uint4 w = make_uint4(0u, 0u, 0u, 0u);
    if (n < Nsrc) {
        const float* r = B + (size_t)n * K + kp * 32 + 2 * q;
        float2 f0 = *(const float2*)r;
        float2 f1 = *(const float2*)(r + 8);
        float2 f2 = *(const float2*)(r + 16);
        float2 f3 = *(const float2*)(r + 24);
        w = make_uint4(h2u(f0.x, f0.y), h2u(f1.x, f1.y),
                       h2u(f2.x, f2.y), h2u(f3.x, f3.y));
    }
    P[idx] = w;
}

// ---------------- embedding gather (fp32 + packed fp16) ----------------
__global__ void embed_kernel(const int* __restrict__ x,
                             const float* __restrict__ embed,
                             float* __restrict__ h,
                             uint32_t* __restrict__ hpk) {
    int bt  = blockIdx.x;
    int tok = x[bt];
    const float4* src = (const float4*)(embed + (size_t)tok * DIM);
    float4 v = src[threadIdx.x];
    ((float4*)(h + (size_t)bt * DIM))[threadIdx.x] = v;
    int c0 = threadIdx.x * 4;
    pk_store(hpk, DIM, bt, c0,     v.x, v.y);
    pk_store(hpk, DIM, bt, c0 + 2, v.z, v.w);
}

// ---------------- packed fp16 GEMM: C[M,N] = A[M,K] B[N,K]^T (+Res) --------
#define ST_W4     2048
#define SMEM_GEMM (3 * ST_W4 * 16)   // 96KB

__global__ void __launch_bounds__(256, 2)
gemm_pk(int N, int K,
        const uint4* __restrict__ Apk,
        const uint4* __restrict__ Bpk,
        const float* __restrict__ Res,
        float* __restrict__ C,
        uint32_t* __restrict__ Cpk) {
    extern __shared__ uint4 sm4[];
    const uint32_t sbase = smem_u32(sm4);

    const int tid    = threadIdx.x;
    const int lane   = tid & 31;
    const int wid    = tid >> 5;
    const int warp_m = wid >> 2;
    const int warp_n = wid & 3;
    const int g      = lane >> 2;
    const int q      = lane & 3;
    const int row0   = blockIdx.y * 128;
    const int col0   = blockIdx.x * 128;
    const int ktn16  = K >> 4;
    const int kpn    = K >> 5;
    const int ktn    = K >> 6;

    const uint4* asrc[4];
    const uint4* bsrc[4];
    uint32_t adst[4], bdst[4];
#pragma unroll
    for (int i = 0; i < 4; i++) {
        int ca = tid + 256 * i;
        int la = ca & 31, r = ca >> 5;
        int ksl = r & 3, mt = r >> 2;
        asrc[i] = Apk + ((size_t)(row0 / 16 + mt) * ktn16 + ksl) * 32 + la;
        adst[i] = ca;
        int kpl = r & 1, nt = r >> 1;
        bsrc[i] = Bpk + ((size_t)(col0 / 8 + nt) * kpn + kpl) * 32 + la;
        bdst[i] = 1024 + ca;
    }

    float acc[4][4][4];
#pragma unroll
    for (int i = 0; i < 4; i++)
#pragma unroll
        for (int j = 0; j < 4; j++)
#pragma unroll
            for (int r = 0; r < 4; r++) acc[i][j][r] = 0.f;

#pragma unroll
    for (int p = 0; p < 2; p++) {
        uint32_t sb = sbase + p * ST_W4 * 16;
#pragma unroll
        for (int i = 0; i < 4; i++) cpa16(sb + adst[i] * 16, asrc[i] + p * 128);
#pragma unroll
        for (int i = 0; i < 4; i++) cpa16(sb + bdst[i] * 16, bsrc[i] + p * 64);
        asm volatile("cp.async.commit_group;");
    }

    for (int kt = 0; kt < ktn; kt++) {
        asm volatile("cp.async.wait_group 1;");
        __syncthreads();

        if (kt + 2 < ktn) {
            uint32_t sb = sbase + ((kt + 2) % 3) * ST_W4 * 16;
            size_t ao = (size_t)(kt + 2) * 128;
            size_t bo = (size_t)(kt + 2) * 64;
#pragma unroll
            for (int i = 0; i < 4; i++) cpa16(sb + adst[i] * 16, asrc[i] + ao);
#pragma unroll
            for (int i = 0; i < 4; i++) cpa16(sb + bdst[i] * 16, bsrc[i] + bo);
        }
        asm volatile("cp.async.commit_group;");

        const uint4* Ab = sm4 + (kt % 3) * ST_W4;
        const uint4* Bb = Ab + 1024;
#pragma unroll
        for (int kp = 0; kp < 2; kp++) {
            uint4 bw[4];
#pragma unroll
            for (int nt = 0; nt < 4; nt++)
                bw[nt] = Bb[((warp_n * 4 + nt) * 2 + kp) * 32 + lane];
#pragma unroll
            for (int hl = 0; hl < 2; hl++) {
                const int ks = kp * 2 + hl;
                uint4 af[4];
#pragma unroll
                for (int mt = 0; mt < 4; mt++)
                    af[mt] = Ab[((warp_m * 4 + mt) * 4 + ks) * 32 + lane];
#pragma unroll
                for (int mt = 0; mt < 4; mt++)
#pragma unroll
                    for (int nt = 0; nt < 4; nt++) {
                        uint32_t b0 = hl ? bw[nt].z : bw[nt].x;
                        uint32_t b1 = hl ? bw[nt].w : bw[nt].y;
                        mma_f16(acc[mt][nt], af[mt].x, af[mt].y, af[mt].z,
                                af[mt].w, b0, b1);
                    }
            }
        }
    }

#pragma unroll
    for (int mt = 0; mt < 4; mt++) {
        int r_lo = row0 + warp_m * 64 + mt * 16 + g;
#pragma unroll
        for (int nt = 0; nt < 4; nt++) {
            int c = col0 + warp_n * 32 + nt * 8 + q * 2;
            if (c < N) {
                float2 v0 = make_float2(acc[mt][nt][0], acc[mt][nt][1]);
                float2 v1 = make_float2(acc[mt][nt][2], acc[mt][nt][3]);
                size_t o0 = (size_t)r_lo * N + c;
                size_t o1 = (size_t)(r_lo + 8) * N + c;
                if (Res) {
                    float2 r0v = *(const float2*)(Res + o0);
                    float2 r1v = *(const float2*)(Res + o1);
                    v0.x += r0v.x; v0.y += r0v.y;
                    v1.x += r1v.x; v1.y += r1v.y;
                }
                *(float2*)(C + o0) = v0;
                *(float2*)(C + o1) = v1;
                if (Cpk) {
                    pk_store(Cpk, N, r_lo,     c, v0.x, v0.y);
                    pk_store(Cpk, N, r_lo + 8, c, v1.x, v1.y);
                }
            }
        }
    }
}

// ---------------- SSM scan v3: conv+silu fused, CTA per (b,h,n-quarter) ----
// 256 CTAs = (4, 32, 2). Thread = (p in 64, nq in 4), owns 8 states.
// Per 16-step chunk: stage raw zx rows [t0-3, t0+16) for x(64)+B(32)+C(32)
// channels, conv+SiLU in smem, then scan. D*x folded into nh==0 partial.
#define SCH   16
#define SROWS (SCH + 3)
__global__ void __launch_bounds__(256)
scan3_kernel(const float* __restrict__ zx,
             const float* __restrict__ cw,
             const float* __restrict__ cb,
             const float* __restrict__ dtb,
             const float* __restrict__ alog,
             const float* __restrict__ Dw,
             float* __restrict__ yp) {
    __shared__ float ZXr[SROWS][64];
    __shared__ float ZBr[SROWS][32];
    __shared__ float ZCr[SROWS][32];
    __shared__ float Xs [SCH][64];
    __shared__ float Bss[SCH][32];
    __shared__ float Css[SCH][32];
    __shared__ float As[SCH], Dts[SCH];
    __shared__ float4 Wf[128];
    __shared__ float  Cbs[128];

    const int tid  = threadIdx.x;
    const int nh   = blockIdx.x;     // n-quarter 0..3
    const int h    = blockIdx.y;
    const int b    = blockIdx.z;
    const int lane = tid & 31;
    const int wid  = tid >> 5;
    const int pl   = lane >> 2;
    const int nq   = lane & 3;
    const int p    = wid * 8 + pl;

    const int xoff = DINNER + h * 64;
    const int boff = DINNER + 2048 + nh * 32;
    const int coff = DINNER + 2176 + nh * 32;

    if (tid < 128) {
        int gc = (tid < 64) ? (h * 64 + tid)
               : (tid < 96) ? (2048 + nh * 32 + tid - 64)
                            : (2176 + nh * 32 + tid - 96);
        Wf[tid]  = *(const float4*)(cw + gc * 4);
        Cbs[tid] = cb[gc];
    }

    float s[8];
#pragma unroll
    for (int i = 0; i < 8; i++) s[i] = 0.f;
    const float dtbv = dtb[h];
    const float aexp = expf(alog[h]);
    const float Dh   = (nh == 0) ? Dw[h] : 0.f;
    const float* zrow = zx + (size_t)b * TT * DINPROJ;
    float* yout = yp + ((size_t)nh * BT + (size_t)b * TT) * DINNER + h * 64;

    for (int t0 = 0; t0 < TT; t0 += SCH) {
        // ---- stage raw zx rows (t0-3 .. t0+SCH-1; t<0 -> 0) ----
        for (int j = tid; j < 608; j += 256) {
            int row, q4, off;
            float* dst;
            if (j < 304)      { row = j / 16;  q4 = j % 16;
                                off = xoff; dst = &ZXr[row][q4 * 4]; }
            else if (j < 456) { int jj = j - 304; row = jj / 8; q4 = jj % 8;
                                off = boff; dst = &ZBr[row][q4 * 4]; }
            else              { int jj = j - 456; row = jj / 8; q4 = jj % 8;
                                off = coff; dst = &ZCr[row][q4 * 4]; }
            int t = t0 - 3 + row;
            float4 v = make_float4(0.f, 0.f, 0.f, 0.f);
            if (t >= 0)
                v = *(const float4*)(zrow + (size_t)t * DINPROJ + off + q4 * 4);
            *(float4*)dst = v;
        }
        if (tid < SCH) {
            float v = zrow[(size_t)(t0 + tid) * DINPROJ + (DINNER + CONVCH) + h]
                      + dtbv;
            float d = (v > 20.f) ? v : log1pf(expf(v));
            Dts[tid] = d;
            As[tid]  = expf(-aexp * d);
        }
        __syncthreads();

        // ---- conv (4-tap) + SiLU into Xs/Bss/Css ----
        for (int j = tid; j < SCH * 128; j += 256) {
            int tt = j >> 7, ch = j & 127;
            float4 w = Wf[ch];
            float acc = Cbs[ch];
            const float* col;
            int stride;
            if (ch < 64)      { col = &ZXr[tt][ch];      stride = 64; }
            else if (ch < 96) { col = &ZBr[tt][ch - 64]; stride = 32; }
            else              { col = &ZCr[tt][ch - 96]; stride = 32; }
            acc = fmaf(col[0],          w.x, acc);
            acc = fmaf(col[stride],     w.y, acc);
            acc = fmaf(col[2 * stride], w.z, acc);
            acc = fmaf(col[3 * stride], w.w, acc);
            acc = acc / (1.f + expf(-acc));
            if (ch < 64) Xs[tt][ch] = acc;
            else {
                int cb2 = (ch < 96) ? ch - 64 : ch - 96;
                int q4  = cb2 >> 2;
                int off2 = ((((q4 & 1) << 2) + (q4 >> 1)) << 2) + (cb2 & 3);
                if (ch < 96) Bss[tt][off2] = acc;
                else         Css[tt][off2] = acc;
            }
        }
        __syncthreads();

        // ---- scan SCH steps ----
#pragma unroll
        for (int tt = 0; tt < SCH; tt++) {
            const float da   = As[tt];
            const float xv   = Xs[tt][p];
            const float coef = Dts[tt] * xv;
            const float4* B4 = (const float4*)&Bss[tt][0];
            const float4* C4 = (const float4*)&Css[tt][0];
            float part = 0.f;
#pragma unroll
            for (int i4 = 0; i4 < 2; i4++) {
                float4 bv = B4[i4 * 4 + nq];
                float4 cv = C4[i4 * 4 + nq];
                float* sp = s + i4 * 4;
                sp[0] = fmaf(da, sp[0], coef * bv.x);
                sp[1] = fmaf(da, sp[1], coef * bv.y);
                sp[2] = fmaf(da, sp[2], coef * bv.z);
                sp[3] = fmaf(da, sp[3], coef * bv.w);
                part = fmaf(sp[0], cv.x, part);
                part = fmaf(sp[1], cv.y, part);
                part = fmaf(sp[2], cv.z, part);
                part = fmaf(sp[3], cv.w, part);
            }
            part += __shfl_xor_sync(0xFFFFFFFFu, part, 1);
            part += __shfl_xor_sync(0xFFFFFFFFu, part, 2);
            if (nq == 0)
                yout[(size_t)(t0 + tt) * DINNER + p] = fmaf(Dh, xv, part);
        }
        __syncthreads();
    }
}

// ---------------- fused gate + RMSNorm + packed write ----------------------
// v = (yp0+yp1+yp2+yp3) * silu(z); out_pk = pack(v * rsqrt(mean v^2+eps) * w)
__global__ void __launch_bounds__(256)
rmsgate_kernel(const float* __restrict__ yp,
               const float* __restrict__ zx,
               const float* __restrict__ w,
               uint32_t* __restrict__ ypk) {
    __shared__ float vc[DINNER];
    __shared__ float sh[9];
    const int bt = blockIdx.x;
    const size_t L = (size_t)BT * DINNER;
    const float* r0 = yp + (size_t)bt * DINNER;
    const float* zr = zx + (size_t)bt * DINPROJ;

    float ss = 0.f;
    for (int i = threadIdx.x * 2; i < DINNER; i += 512) {
        float2 a0 = *(const float2*)(r0 + i);
        float2 a1 = *(const float2*)(r0 + L + i);
        float2 a2 = *(const float2*)(r0 + 2 * L + i);
        float2 a3 = *(const float2*)(r0 + 3 * L + i);
        float2 z2 = *(const float2*)(zr + i);
        float y0 = a0.x + a1.x + a2.x + a3.x;
        float y1 = a0.y + a1.y + a2.y + a3.y;
        float v0 = y0 * (z2.x / (1.f + expf(-z2.x)));
        float v1 = y1 * (z2.y / (1.f + expf(-z2.y)));
        vc[i] = v0; vc[i + 1] = v1;
        ss = fmaf(v0, v0, fmaf(v1, v1, ss));
    }
#pragma unroll
    for (int o = 16; o; o >>= 1) ss += __shfl_xor_sync(0xFFFFFFFFu, ss, o);
    int wd = threadIdx.x >> 5, lane = threadIdx.x & 31;
    if (lane == 0) sh[wd] = ss;
    __syncthreads();
    if (wd == 0) {
        float v = (lane < 8) ? sh[lane] : 0.f;
#pragma unroll
        for (int o = 16; o; o >>= 1) v += __shfl_xor_sync(0xFFFFFFFFu, v, o);
        if (lane == 0) sh[8] = rsqrtf(v / DINNER + 1e-5f);
    }
    __syncthreads();
    float sc = sh[8];
    for (int i = threadIdx.x * 2; i < DINNER; i += 512) {
        float o0 = vc[i] * sc * w[i];
        float o1 = vc[i + 1] * sc * w[i + 1];
        pk_store(ypk, DINNER, bt, i, o0, o1);
    }
}

// ---------------- final RMSNorm (+ packed write) ----------------
__global__ void rmsnorm_kernel(float* __restrict__ data,
                               const float* __restrict__ w, int n,
                               uint32_t* __restrict__ pk) {
    float* r = data + (size_t)blockIdx.x * n;
    float ss = 0.f;
    for (int i = threadIdx.x; i < n; i += blockDim.x) {
        float v = r[i];
        ss = fmaf(v, v, ss);
    }
#pragma unroll
    for (int o = 16; o; o >>= 1) ss += __shfl_xor_sync(0xFFFFFFFFu, ss, o);
    __shared__ float sh[9];
    int wd = threadIdx.x >> 5, lane = threadIdx.x & 31;
    if (lane == 0) sh[wd] = ss;
    __syncthreads();
    if (wd == 0) {
        float v = (lane < 8) ? sh[lane] : 0.f;
#pragma unroll
        for (int o = 16; o; o >>= 1) v += __shfl_xor_sync(0xFFFFFFFFu, v, o);
        if (lane == 0) sh[8] = rsqrtf(v / n + 1e-5f);
    }
    __syncthreads();
    float sc = sh[8];
    for (int i = threadIdx.x * 2; i < n; i += 2 * blockDim.x) {
        float o0 = r[i] * sc * w[i];
        float o1 = r[i + 1] * sc * w[i + 1];
        r[i] = o0; r[i + 1] = o1;
        pk_store(pk, n, blockIdx.x, i, o0, o1);
    }
}

// ---------------- launcher ----------------
extern "C" void kernel_launch(void* const* d_in, const int* in_sizes, int n_in,
                              void* d_out, int out_size) {
    const int*   x            = (const int*)  d_in[0];
    const float* embed        = (const float*)d_in[1];
    const float* in_proj_w    = (const float*)d_in[2];
    const float* conv_w       = (const float*)d_in[3];
    const float* conv_b       = (const float*)d_in[4];
    const float* dt_bias      = (const float*)d_in[5];
    const float* A_log        = (const float*)d_in[6];
    const float* Dw           = (const float*)d_in[7];
    const float* gnorm_w      = (const float*)d_in[8];
    const float* out_proj_w   = (const float*)d_in[9];
    const float* final_norm_w = (const float*)d_in[10];
    float* out = (float*)d_out;

    float *ph, *pzx, *pyp;
    uint4 *pwin, *pwout, *pemb, *phpk, *pypk;
    cudaGetSymbolAddress((void**)&ph,    g_h);
    cudaGetSymbolAddress((void**)&pzx,   g_zx);
    cudaGetSymbolAddress((void**)&pyp,   g_yp);
    cudaGetSymbolAddress((void**)&pwin,  g_win_pk);
    cudaGetSymbolAddress((void**)&pwout, g_wout_pk);
    cudaGetSymbolAddress((void**)&pemb,  g_emb_pk);
    cudaGetSymbolAddress((void**)&phpk,  g_h_pk);
    cudaGetSymbolAddress((void**)&pypk,  g_y_pk);
    uint32_t* phpk32 = (uint32_t*)phpk;
    uint32_t* pypk32 = (uint32_t*)pypk;

    cudaFuncSetAttribute(gemm_pk, cudaFuncAttributeMaxDynamicSharedMemorySize,
                         SMEM_GEMM);

    const int WIN_W  = (NPAD_IN / 8) * (DIM / 32) * 32;
    const int WOUT_W = (DIM / 8) * (DINNER / 32) * 32;
    const int EMB_W  = (VOCAB / 8) * (DIM / 32) * 32;

    // launches 1-5; launch 6 = scan3 of layer 0 (ncu -s 5 -c 1 window)
    pack_b<<<WIN_W / 256, 256>>>(in_proj_w, pwin, DIM, DINPROJ);
    pack_b<<<WIN_W / 256, 256>>>(in_proj_w + (size_t)DINPROJ * DIM,
                                 pwin + WIN_W, DIM, DINPROJ);
    pack_b<<<EMB_W / 256, 256>>>(embed, pemb, DIM, VOCAB);
    embed_kernel<<<BT, 256>>>(x, embed, ph, phpk32);

    for (int l = 0; l < DEPTH; l++) {
        gemm_pk<<<dim3(NPAD_IN / 128, BT / 128), 256, SMEM_GEMM>>>(
            DINPROJ, DIM, phpk, pwin + (size_t)l * WIN_W, nullptr, pzx,
            nullptr);
        scan3_kernel<<<dim3(4, NHEADS, BB), 256>>>(
            pzx, conv_w + (size_t)l * CONVCH * 4, conv_b + (size_t)l * CONVCH,
            dt_bias + l * NHEADS, A_log + l * NHEADS, Dw + l * NHEADS, pyp);
        pack_b<<<WOUT_W / 256, 256>>>(out_proj_w + (size_t)l * DIM * DINNER,
                                      pwout + (size_t)l * WOUT_W, DINNER, DIM);
        rmsgate_kernel<<<BT, 256>>>(pyp, pzx, gnorm_w + (size_t)l * DINNER,
                                    pypk32);
        gemm_pk<<<dim3(DIM / 128, BT / 128), 256, SMEM_GEMM>>>(
            DIM, DINNER, pypk, pwout + (size_t)l * WOUT_W, ph, ph, phpk32);
    }

    rmsnorm_kernel<<<BT, 256>>>(ph, final_norm_w, DIM, phpk32);
    gemm_pk<<<dim3(VOCAB / 128, BT / 128), 256, SMEM_GEMM>>>(
        VOCAB, DIM, phpk, pemb, nullptr, out, nullptr);
}